// round 2
// baseline (speedup 1.0000x reference)
#include <cuda_runtime.h>
#include <math.h>

#define NB   4
#define LSEQ 4096
#define EDIM 1024
#define HDIM 1024
#define ML   (NB * LSEQ)   // 16384 total rows

typedef unsigned long long u64;

// Scratch (static __device__ arrays: allowed; no allocation APIs used)
__device__ float g_Q[ML * HDIM];       // 64 MB
__device__ float g_K[ML * HDIM];       // 64 MB
__device__ float g_V[ML * HDIM];       // 64 MB
__device__ float g_colsum[ML];
__device__ float g_diag[ML];

// Packed fp32x2 FMA (Blackwell FFMA2): d = a*b + c elementwise on both halves
__device__ __forceinline__ u64 ffma2(u64 a, u64 b, u64 c) {
    asm("fma.rn.f32x2 %0, %1, %2, %0;" : "+l"(c) : "l"(a), "l"(b));
    return c;
}

// ---------------------------------------------------------------------------
// Shared 128x128x8 double-buffered mainloop.
//   Asd: A operand duplicated per element  -> [2][8][256] (pairs (a,a))
//   Bs : B operand (row n of W / K)        -> [2][8][128]
// Thread (tx=tid&15, ty=tid>>4) computes rows ty*8..+7, cols tx*8..+7
// acc[mi][nj] = f32x2 over column pair (tx*8+2nj, tx*8+2nj+1), row ty*8+mi
// ---------------------------------------------------------------------------
#define STS_TILE(buf) do {                                                  \
    *(float2*)&Asd[buf][lk+0][2*lr] = make_float2(pa.x, pa.x);              \
    *(float2*)&Asd[buf][lk+1][2*lr] = make_float2(pa.y, pa.y);              \
    *(float2*)&Asd[buf][lk+2][2*lr] = make_float2(pa.z, pa.z);              \
    *(float2*)&Asd[buf][lk+3][2*lr] = make_float2(pa.w, pa.w);              \
    Bs[buf][lk+0][lr] = pb.x;                                               \
    Bs[buf][lk+1][lr] = pb.y;                                               \
    Bs[buf][lk+2][lr] = pb.z;                                               \
    Bs[buf][lk+3][lr] = pb.w;                                               \
} while (0)

__device__ __forceinline__ void gemm_mainloop(
    const float* Aptr, const float* Bptr,
    float (&Asd)[2][8][256], float (&Bs)[2][8][128],
    int tx, int ty, int lr, int lk, u64 (&acc)[8][4])
{
    float4 pa = *(const float4*)Aptr;
    float4 pb = *(const float4*)Bptr;
    Aptr += 8; Bptr += 8;
    STS_TILE(0);
    __syncthreads();

#pragma unroll 1
    for (int kt = 0; kt < 128; kt++) {
        const int cur = kt & 1;
        if (kt < 127) {
            pa = *(const float4*)Aptr;
            pb = *(const float4*)Bptr;
            Aptr += 8; Bptr += 8;
        }
#pragma unroll
        for (int ks = 0; ks < 8; ks++) {
            const u64* ap = (const u64*)&Asd[cur][ks][ty * 16];
            const u64* bp = (const u64*)&Bs[cur][ks][tx * 8];
            u64 a2[8], b2[4];
#pragma unroll
            for (int i = 0; i < 8; i++) a2[i] = ap[i];
#pragma unroll
            for (int j = 0; j < 4; j++) b2[j] = bp[j];
#pragma unroll
            for (int i = 0; i < 8; i++)
#pragma unroll
                for (int j = 0; j < 4; j++)
                    acc[i][j] = ffma2(a2[i], b2[j], acc[i][j]);
        }
        if (kt < 127) {
            const int nxt = cur ^ 1;
            STS_TILE(nxt);
            __syncthreads();
        }
    }
}

// ---------------------------------------------------------------------------
// Kernel 1: Q/K/V projections.  out[m, n] = sum_e X[m, e] * W[n, e] + b[n]
// grid: (HDIM/128, ML/128, 3)   z selects (Wq,bq,gQ) / (Wk,...) / (Wv,...)
// ---------------------------------------------------------------------------
__global__ void __launch_bounds__(256) qkv_kernel(
    const float* __restrict__ X,
    const float* __restrict__ Wq, const float* __restrict__ bq,
    const float* __restrict__ Wk, const float* __restrict__ bk,
    const float* __restrict__ Wv, const float* __restrict__ bv)
{
    __shared__ __align__(16) float Asd[2][8][256];
    __shared__ __align__(16) float Bs[2][8][128];

    const float* W; const float* bias; float* out;
    if (blockIdx.z == 0)      { W = Wq; bias = bq; out = g_Q; }
    else if (blockIdx.z == 1) { W = Wk; bias = bk; out = g_K; }
    else                      { W = Wv; bias = bv; out = g_V; }

    const int tid = threadIdx.x;
    const int tx = tid & 15, ty = tid >> 4;
    const int lr = tid >> 1, lk = (tid & 1) * 4;
    const int m0 = blockIdx.y * 128, n0 = blockIdx.x * 128;

    const float* Aptr = X + (size_t)(m0 + lr) * EDIM + lk;
    const float* Bptr = W + (size_t)(n0 + lr) * EDIM + lk;

    u64 acc[8][4] = {};
    gemm_mainloop(Aptr, Bptr, Asd, Bs, tx, ty, lr, lk, acc);

    float bcol[8];
#pragma unroll
    for (int j = 0; j < 8; j++) bcol[j] = bias[n0 + tx * 8 + j];

#pragma unroll
    for (int mi = 0; mi < 8; mi++) {
        float* orow = out + (size_t)(m0 + ty * 8 + mi) * HDIM + n0 + tx * 8;
#pragma unroll
        for (int nj = 0; nj < 4; nj++) {
            float2 c = *(float2*)&acc[mi][nj];
            c.x += bcol[2 * nj];
            c.y += bcol[2 * nj + 1];
            *(float2*)(orow + 2 * nj) = c;
        }
    }
}

// ---------------------------------------------------------------------------
// Kernel 2: streaming scores.  S[a,b] = Q[a]·K[b] / sqrt(L)
// Accumulates colsum[b] += sum_a exp(S[a,b]); captures diag exp(S[l,l]).
// grid: (LSEQ/128, LSEQ/128, NB)
// ---------------------------------------------------------------------------
__global__ void __launch_bounds__(256) scores_kernel()
{
    __shared__ __align__(16) float Asd[2][8][256];
    __shared__ __align__(16) float Bs[2][8][128];
    __shared__ float red[16][128];

    const int bz = blockIdx.z;
    const float* Qb = g_Q + (size_t)bz * LSEQ * HDIM;
    const float* Kb = g_K + (size_t)bz * LSEQ * HDIM;

    const int tid = threadIdx.x;
    const int tx = tid & 15, ty = tid >> 4;
    const int lr = tid >> 1, lk = (tid & 1) * 4;
    const int m0 = blockIdx.y * 128, n0 = blockIdx.x * 128;

    const float* Aptr = Qb + (size_t)(m0 + lr) * HDIM + lk;
    const float* Bptr = Kb + (size_t)(n0 + lr) * HDIM + lk;

    u64 acc[8][4] = {};
    gemm_mainloop(Aptr, Bptr, Asd, Bs, tx, ty, lr, lk, acc);

    const float sc = 0.015625f;  // 1/sqrt(4096)
    float colp[8];
#pragma unroll
    for (int j = 0; j < 8; j++) colp[j] = 0.0f;

#pragma unroll
    for (int mi = 0; mi < 8; mi++) {
        const int mg = m0 + ty * 8 + mi;
#pragma unroll
        for (int nj = 0; nj < 4; nj++) {
            float2 s = *(float2*)&acc[mi][nj];
            float e0 = expf(s.x * sc);
            float e1 = expf(s.y * sc);
            colp[2 * nj]     += e0;
            colp[2 * nj + 1] += e1;
            const int ng = n0 + tx * 8 + 2 * nj;
            if (mg == ng)     g_diag[bz * LSEQ + mg] = e0;
            if (mg == ng + 1) g_diag[bz * LSEQ + mg] = e1;
        }
    }

#pragma unroll
    for (int j = 0; j < 8; j++) red[ty][tx * 8 + j] = colp[j];
    __syncthreads();

    if (tid < 128) {
        float s = 0.0f;
#pragma unroll
        for (int t = 0; t < 16; t++) s += red[t][tid];
        atomicAdd(&g_colsum[bz * LSEQ + n0 + tid], s);
    }
}

// ---------------------------------------------------------------------------
// Kernel 3: out[n,l,h] = (diag / colsum) * V[n,l,h]
// ---------------------------------------------------------------------------
__global__ void __launch_bounds__(256) finalize_kernel(float* __restrict__ out)
{
    const int row = blockIdx.x;             // 0..ML-1
    const float scale = g_diag[row] / g_colsum[row];
    const float4* v = (const float4*)(g_V + (size_t)row * HDIM);
    float4* o = (float4*)(out + (size_t)row * HDIM);
    float4 x = v[threadIdx.x];
    x.x *= scale; x.y *= scale; x.z *= scale; x.w *= scale;
    o[threadIdx.x] = x;
}

__global__ void zero_kernel()
{
    const int i = blockIdx.x * 256 + threadIdx.x;
    if (i < ML) g_colsum[i] = 0.0f;
}

// ---------------------------------------------------------------------------
extern "C" void kernel_launch(void* const* d_in, const int* in_sizes, int n_in,
                              void* d_out, int out_size)
{
    (void)in_sizes; (void)n_in; (void)out_size;
    const float* X  = (const float*)d_in[0];
    const float* Wq = (const float*)d_in[1];
    const float* bq = (const float*)d_in[2];
    const float* Wk = (const float*)d_in[3];
    const float* bk = (const float*)d_in[4];
    const float* Wv = (const float*)d_in[5];
    const float* bv = (const float*)d_in[6];
    float* out = (float*)d_out;

    zero_kernel<<<(ML + 255) / 256, 256>>>();

    dim3 g1(HDIM / 128, ML / 128, 3);
    qkv_kernel<<<g1, 256>>>(X, Wq, bq, Wk, bk, Wv, bv);

    dim3 g2(LSEQ / 128, LSEQ / 128, NB);
    scores_kernel<<<g2, 256>>>();

    finalize_kernel<<<ML, 256>>>(out);
}

// round 4
// speedup vs baseline: 3.0782x; 3.0782x over previous
#include <cuda_runtime.h>
#include <cuda_bf16.h>
#include <math.h>
#include <stdint.h>

#define NB   4
#define LSEQ 4096
#define EDIM 1024
#define HDIM 1024
#define ML   (NB * LSEQ)      // 16384

// ---------------- scratch (static device arrays; no allocation APIs) -------
__device__ __nv_bfloat16 g_Xhi[ML * EDIM];
__device__ __nv_bfloat16 g_Xlo[ML * EDIM];
__device__ __nv_bfloat16 g_Whi[3 * HDIM * EDIM];
__device__ __nv_bfloat16 g_Wlo[3 * HDIM * EDIM];
__device__ __nv_bfloat16 g_Qhi[ML * HDIM];
__device__ __nv_bfloat16 g_Qlo[ML * HDIM];
__device__ __nv_bfloat16 g_Khi[ML * HDIM];
__device__ __nv_bfloat16 g_Klo[ML * HDIM];
__device__ float         g_V[ML * HDIM];
__device__ float         g_colsum[ML];
__device__ float         g_diag[ML];

// ---------------- helpers --------------------------------------------------
__device__ __forceinline__ uint32_t smem_u32(const void* p) {
    uint32_t a;
    asm("{ .reg .u64 t; cvta.to.shared.u64 t, %1; cvt.u32.u64 %0, t; }"
        : "=r"(a) : "l"(p));
    return a;
}

__device__ __forceinline__ void cp16(uint32_t s, const void* g) {
    asm volatile("cp.async.cg.shared.global [%0], [%1], 16;" :: "r"(s), "l"(g));
}
#define CP_COMMIT() asm volatile("cp.async.commit_group;" ::: "memory")
#define CP_WAIT1()  asm volatile("cp.async.wait_group 1;" ::: "memory")
#define CP_WAIT0()  asm volatile("cp.async.wait_group 0;" ::: "memory")

__device__ __forceinline__ void ldsm4(uint32_t* a, uint32_t addr) {
    asm volatile("ldmatrix.sync.aligned.m8n8.x4.shared.b16 {%0,%1,%2,%3}, [%4];"
                 : "=r"(a[0]), "=r"(a[1]), "=r"(a[2]), "=r"(a[3]) : "r"(addr));
}
__device__ __forceinline__ void ldsm2(uint32_t* b, uint32_t addr) {
    asm volatile("ldmatrix.sync.aligned.m8n8.x2.shared.b16 {%0,%1}, [%2];"
                 : "=r"(b[0]), "=r"(b[1]) : "r"(addr));
}
__device__ __forceinline__ void mma16816(float* d, const uint32_t* a, const uint32_t* b) {
    asm volatile(
        "mma.sync.aligned.m16n8k16.row.col.f32.bf16.bf16.f32 "
        "{%0,%1,%2,%3}, {%4,%5,%6,%7}, {%8,%9}, {%0,%1,%2,%3};"
        : "+f"(d[0]), "+f"(d[1]), "+f"(d[2]), "+f"(d[3])
        : "r"(a[0]), "r"(a[1]), "r"(a[2]), "r"(a[3]), "r"(b[0]), "r"(b[1]));
}

// ---------------- tiling constants -----------------------------------------
#define PITCH   80                    // bytes per smem row (32 bf16 + 16B pad)
#define TSZ     (128 * PITCH)         // one operand tile: 10240 B
#define STG     (4 * TSZ)             // Ah, Al, Bh, Bl per stage: 40960 B
#define DYNSMEM (2 * STG)             // double buffered: 81920 B

// ---------------------------------------------------------------------------
// Core: 128x128 output tile via split-bf16 (hi*hi + hi*lo + lo*hi) mma.sync.
// acc[mi][ni][4]: warp (wm,wn) owns rows wm*64+mi*16, cols wn*32+ni*8.
// ---------------------------------------------------------------------------
__device__ __forceinline__ void run_tile(
    const __nv_bfloat16* __restrict__ Ah, const __nv_bfloat16* __restrict__ Al,
    const __nv_bfloat16* __restrict__ Bh, const __nv_bfloat16* __restrict__ Bl,
    int m0, int n0, int Kdim, char* sm, float (&acc)[4][4][4])
{
    const int tid  = threadIdx.x;
    const int wid  = tid >> 5, lane = tid & 31;
    const int wm   = wid >> 2, wn = wid & 3;
    const uint32_t sbase = smem_u32(sm);

    // staging: thread covers 32B (16 bf16) of one row of each operand tile
    const int r  = tid >> 1, cg = tid & 1;
    const size_t ga = (size_t)(m0 + r) * Kdim + cg * 16;
    const size_t gb = (size_t)(n0 + r) * Kdim + cg * 16;
    const uint32_t soff = (uint32_t)(r * PITCH + cg * 32);

    // ldmatrix per-lane byte offsets within an operand tile
    const uint32_t aoff = (uint32_t)((wm * 64 + (lane & 15)) * PITCH + (lane >> 4) * 16);
    const uint32_t boff = (uint32_t)((wn * 32 + (lane & 7)) * PITCH + ((lane >> 3) & 1) * 16);

#define LOADC(st, kc) do {                                                    \
    const uint32_t s0 = sbase + (uint32_t)(st) * STG + soff;                  \
    cp16(s0 + 0 * TSZ,      Ah + ga + (kc));                                  \
    cp16(s0 + 0 * TSZ + 16, Ah + ga + (kc) + 8);                              \
    cp16(s0 + 1 * TSZ,      Al + ga + (kc));                                  \
    cp16(s0 + 1 * TSZ + 16, Al + ga + (kc) + 8);                              \
    cp16(s0 + 2 * TSZ,      Bh + gb + (kc));                                  \
    cp16(s0 + 2 * TSZ + 16, Bh + gb + (kc) + 8);                              \
    cp16(s0 + 3 * TSZ,      Bl + gb + (kc));                                  \
    cp16(s0 + 3 * TSZ + 16, Bl + gb + (kc) + 8);                              \
    CP_COMMIT();                                                              \
} while (0)

    const int NC = Kdim / 32;
    LOADC(0, 0);

#pragma unroll 1
    for (int c = 0; c < NC; c++) {
        if (c + 1 < NC) { LOADC((c + 1) & 1, (c + 1) * 32); CP_WAIT1(); }
        else            { CP_WAIT0(); }
        __syncthreads();

        const uint32_t tb = sbase + (uint32_t)(c & 1) * STG;
#pragma unroll
        for (int k16 = 0; k16 < 2; k16++) {
            uint32_t ah[4][4], al[4][4], bh[4][2], bl[4][2];
#pragma unroll
            for (int mi = 0; mi < 4; mi++) {
                ldsm4(ah[mi], tb + 0 * TSZ + aoff + mi * 16 * PITCH + k16 * 32);
                ldsm4(al[mi], tb + 1 * TSZ + aoff + mi * 16 * PITCH + k16 * 32);
            }
#pragma unroll
            for (int ni = 0; ni < 4; ni++) {
                ldsm2(bh[ni], tb + 2 * TSZ + boff + ni * 8 * PITCH + k16 * 32);
                ldsm2(bl[ni], tb + 3 * TSZ + boff + ni * 8 * PITCH + k16 * 32);
            }
#pragma unroll
            for (int mi = 0; mi < 4; mi++)
#pragma unroll
                for (int ni = 0; ni < 4; ni++) {
                    mma16816(acc[mi][ni], ah[mi], bh[ni]);
                    mma16816(acc[mi][ni], ah[mi], bl[ni]);
                    mma16816(acc[mi][ni], al[mi], bh[ni]);
                }
        }
        __syncthreads();
    }
#undef LOADC
}

// ---------------------------------------------------------------------------
// Conversions fp32 -> (bf16 hi, bf16 lo)
// ---------------------------------------------------------------------------
__device__ __forceinline__ void split4(float4 v, __nv_bfloat162& h0, __nv_bfloat162& h1,
                                       __nv_bfloat162& l0, __nv_bfloat162& l1) {
    float f[4] = {v.x, v.y, v.z, v.w};
    __nv_bfloat16 h[4], l[4];
#pragma unroll
    for (int i = 0; i < 4; i++) {
        h[i] = __float2bfloat16(f[i]);
        l[i] = __float2bfloat16(f[i] - __bfloat162float(h[i]));
    }
    h0.x = h[0]; h0.y = h[1]; h1.x = h[2]; h1.y = h[3];
    l0.x = l[0]; l0.y = l[1]; l1.x = l[2]; l1.y = l[3];
}

__global__ void __launch_bounds__(256) convx_kernel(const float* __restrict__ X) {
    const size_t i = (size_t)blockIdx.x * 256 + threadIdx.x;   // float4 index
    float4 v = ((const float4*)X)[i];
    __nv_bfloat162 h0, h1, l0, l1;
    split4(v, h0, h1, l0, l1);
    ((__nv_bfloat162*)g_Xhi)[2 * i]     = h0;
    ((__nv_bfloat162*)g_Xhi)[2 * i + 1] = h1;
    ((__nv_bfloat162*)g_Xlo)[2 * i]     = l0;
    ((__nv_bfloat162*)g_Xlo)[2 * i + 1] = l1;
}

__global__ void __launch_bounds__(256) convw_kernel(
    const float* __restrict__ Wq, const float* __restrict__ Wk,
    const float* __restrict__ Wv)
{
    const float* W = blockIdx.z == 0 ? Wq : blockIdx.z == 1 ? Wk : Wv;
    const size_t i = (size_t)blockIdx.x * 256 + threadIdx.x;
    const size_t zoff = (size_t)blockIdx.z * (HDIM * (size_t)EDIM / 2);
    float4 v = ((const float4*)W)[i];
    __nv_bfloat162 h0, h1, l0, l1;
    split4(v, h0, h1, l0, l1);
    ((__nv_bfloat162*)g_Whi)[zoff + 2 * i]     = h0;
    ((__nv_bfloat162*)g_Whi)[zoff + 2 * i + 1] = h1;
    ((__nv_bfloat162*)g_Wlo)[zoff + 2 * i]     = l0;
    ((__nv_bfloat162*)g_Wlo)[zoff + 2 * i + 1] = l1;
}

// ---------------------------------------------------------------------------
// GEMM1: Q/K/V projections.  D[m,n] = X[m,:]·W[n,:] + bias[n]
// grid (HDIM/128, ML/128, 3); z: 0->Q, 1->K (bf16 hi/lo), 2->V (fp32)
// ---------------------------------------------------------------------------
__global__ void __launch_bounds__(256) gemm1_kernel(
    const float* __restrict__ bq, const float* __restrict__ bk,
    const float* __restrict__ bv)
{
    extern __shared__ char dynsm[];
    const int z  = blockIdx.z;
    const int m0 = blockIdx.y * 128;
    const int n0 = blockIdx.x * 128;

    const __nv_bfloat16* Bh = g_Whi + (size_t)z * HDIM * EDIM;
    const __nv_bfloat16* Bl = g_Wlo + (size_t)z * HDIM * EDIM;

    float acc[4][4][4];
#pragma unroll
    for (int a = 0; a < 4; a++)
#pragma unroll
        for (int b = 0; b < 4; b++)
#pragma unroll
            for (int cc = 0; cc < 4; cc++) acc[a][b][cc] = 0.0f;

    run_tile(g_Xhi, g_Xlo, Bh, Bl, m0, n0, EDIM, dynsm, acc);

    const float* bias = z == 0 ? bq : z == 1 ? bk : bv;
    __nv_bfloat16* oh = z == 0 ? g_Qhi : g_Khi;
    __nv_bfloat16* ol = z == 0 ? g_Qlo : g_Klo;

    const int tid = threadIdx.x;
    const int wid = tid >> 5, lane = tid & 31;
    const int wm = wid >> 2, wn = wid & 3;

#pragma unroll
    for (int mi = 0; mi < 4; mi++) {
        const int r0 = m0 + wm * 64 + mi * 16 + (lane >> 2);
#pragma unroll
        for (int ni = 0; ni < 4; ni++) {
            const int gc = n0 + wn * 32 + ni * 8 + 2 * (lane & 3);
            const float b0 = __ldg(&bias[gc]), b1 = __ldg(&bias[gc + 1]);
            const float v00 = acc[mi][ni][0] + b0, v01 = acc[mi][ni][1] + b1;
            const float v10 = acc[mi][ni][2] + b0, v11 = acc[mi][ni][3] + b1;
            if (z == 2) {
                *(float2*)(g_V + (size_t)r0 * HDIM + gc)       = make_float2(v00, v01);
                *(float2*)(g_V + (size_t)(r0 + 8) * HDIM + gc) = make_float2(v10, v11);
            } else {
                __nv_bfloat162 hh, ll;
                hh.x = __float2bfloat16(v00);
                hh.y = __float2bfloat16(v01);
                ll.x = __float2bfloat16(v00 - __bfloat162float(hh.x));
                ll.y = __float2bfloat16(v01 - __bfloat162float(hh.y));
                *(__nv_bfloat162*)(oh + (size_t)r0 * HDIM + gc) = hh;
                *(__nv_bfloat162*)(ol + (size_t)r0 * HDIM + gc) = ll;
                hh.x = __float2bfloat16(v10);
                hh.y = __float2bfloat16(v11);
                ll.x = __float2bfloat16(v10 - __bfloat162float(hh.x));
                ll.y = __float2bfloat16(v11 - __bfloat162float(hh.y));
                *(__nv_bfloat162*)(oh + (size_t)(r0 + 8) * HDIM + gc) = hh;
                *(__nv_bfloat162*)(ol + (size_t)(r0 + 8) * HDIM + gc) = ll;
            }
        }
    }
}

// ---------------------------------------------------------------------------
// GEMM2: S[a,b] = Q[a]·K[b]/64; fused exp + colsum + diag. No S materialized.
// grid (LSEQ/128, LSEQ/128, NB)
// ---------------------------------------------------------------------------
__global__ void __launch_bounds__(256) gemm2_kernel()
{
    extern __shared__ char dynsm[];
    __shared__ float sred[128];

    const int bz = blockIdx.z;
    const int m0 = blockIdx.y * 128;
    const int n0 = blockIdx.x * 128;
    const int tid = threadIdx.x;

    if (tid < 128) sred[tid] = 0.0f;

    const size_t bo = (size_t)bz * LSEQ * HDIM;
    float acc[4][4][4];
#pragma unroll
    for (int a = 0; a < 4; a++)
#pragma unroll
        for (int b = 0; b < 4; b++)
#pragma unroll
            for (int cc = 0; cc < 4; cc++) acc[a][b][cc] = 0.0f;

    run_tile(g_Qhi + bo, g_Qlo + bo, g_Khi + bo, g_Klo + bo,
             m0, n0, HDIM, dynsm, acc);

    const int wid = tid >> 5, lane = tid & 31;
    const int wm = wid >> 2, wn = wid & 3;
    const float sc = 0.015625f;   // 1/sqrt(4096)
    const bool diagblk = (blockIdx.x == blockIdx.y);

    float2 csum[4];
#pragma unroll
    for (int ni = 0; ni < 4; ni++) csum[ni] = make_float2(0.0f, 0.0f);

#pragma unroll
    for (int mi = 0; mi < 4; mi++) {
        const int lr = wm * 64 + mi * 16 + (lane >> 2);
#pragma unroll
        for (int ni = 0; ni < 4; ni++) {
            const int lc = wn * 32 + ni * 8 + 2 * (lane & 3);
            const float e00 = __expf(acc[mi][ni][0] * sc);
            const float e01 = __expf(acc[mi][ni][1] * sc);
            const float e10 = __expf(acc[mi][ni][2] * sc);
            const float e11 = __expf(acc[mi][ni][3] * sc);
            csum[ni].x += e00 + e10;
            csum[ni].y += e01 + e11;
            if (diagblk) {
                if (lr == lc)         g_diag[(size_t)bz * LSEQ + m0 + lr] = e00;
                if (lr == lc + 1)     g_diag[(size_t)bz * LSEQ + m0 + lr] = e01;
                if (lr + 8 == lc)     g_diag[(size_t)bz * LSEQ + m0 + lr + 8] = e10;
                if (lr + 8 == lc + 1) g_diag[(size_t)bz * LSEQ + m0 + lr + 8] = e11;
            }
        }
    }

#pragma unroll
    for (int ni = 0; ni < 4; ni++) {
#pragma unroll
        for (int m = 4; m <= 16; m <<= 1) {
            csum[ni].x += __shfl_xor_sync(0xffffffffu, csum[ni].x, m);
            csum[ni].y += __shfl_xor_sync(0xffffffffu, csum[ni].y, m);
        }
        if (lane < 4) {
            atomicAdd(&sred[wn * 32 + ni * 8 + 2 * lane],     csum[ni].x);
            atomicAdd(&sred[wn * 32 + ni * 8 + 2 * lane + 1], csum[ni].y);
        }
    }

    __syncthreads();
    if (tid < 128)
        atomicAdd(&g_colsum[(size_t)bz * LSEQ + n0 + tid], sred[tid]);
}

// ---------------------------------------------------------------------------
__global__ void __launch_bounds__(256) finalize_kernel(float* __restrict__ out)
{
    const int row = blockIdx.x;
    const float scale = g_diag[row] / g_colsum[row];
    const float4* v = (const float4*)(g_V + (size_t)row * HDIM);
    float4* o = (float4*)(out + (size_t)row * HDIM);
    float4 x = v[threadIdx.x];
    x.x *= scale; x.y *= scale; x.z *= scale; x.w *= scale;
    o[threadIdx.x] = x;
}

__global__ void zero_kernel()
{
    const int i = blockIdx.x * 256 + threadIdx.x;
    if (i < ML) g_colsum[i] = 0.0f;
}

// ---------------------------------------------------------------------------
extern "C" void kernel_launch(void* const* d_in, const int* in_sizes, int n_in,
                              void* d_out, int out_size)
{
    (void)in_sizes; (void)n_in; (void)out_size;
    const float* X  = (const float*)d_in[0];
    const float* Wq = (const float*)d_in[1];
    const float* bq = (const float*)d_in[2];
    const float* Wk = (const float*)d_in[3];
    const float* bk = (const float*)d_in[4];
    const float* Wv = (const float*)d_in[5];
    const float* bv = (const float*)d_in[6];
    float* out = (float*)d_out;

    static int smem_set = 0;
    if (!smem_set) {
        cudaFuncSetAttribute(gemm1_kernel, cudaFuncAttributeMaxDynamicSharedMemorySize, DYNSMEM);
        cudaFuncSetAttribute(gemm2_kernel, cudaFuncAttributeMaxDynamicSharedMemorySize, DYNSMEM);
        smem_set = 1;
    }

    zero_kernel<<<(ML + 255) / 256, 256>>>();

    convx_kernel<<<(ML * EDIM / 4) / 256, 256>>>(X);
    dim3 gw((HDIM * EDIM / 4) / 256, 1, 3);
    convw_kernel<<<gw, 256>>>(Wq, Wk, Wv);

    dim3 g1(HDIM / 128, ML / 128, 3);
    gemm1_kernel<<<g1, 256, DYNSMEM>>>(bq, bk, bv);

    dim3 g2(LSEQ / 128, LSEQ / 128, NB);
    gemm2_kernel<<<g2, 256, DYNSMEM>>>();

    finalize_kernel<<<ML, 256>>>(out);
}

// round 6
// speedup vs baseline: 4.4570x; 1.4479x over previous
#include <cuda_runtime.h>
#include <cuda_bf16.h>
#include <math.h>
#include <stdint.h>

#define NB   4
#define LSEQ 4096
#define EDIM 1024
#define HDIM 1024
#define ML   (NB * LSEQ)      // 16384

// ---------------- scratch (static device arrays; no allocation APIs) -------
__device__ __nv_bfloat16 g_Xhi[ML * EDIM];
__device__ __nv_bfloat16 g_Xlo[ML * EDIM];
__device__ __nv_bfloat16 g_Whi[3 * HDIM * EDIM];
__device__ __nv_bfloat16 g_Wlo[3 * HDIM * EDIM];
__device__ __nv_bfloat16 g_Qhi[ML * HDIM];
__device__ __nv_bfloat16 g_Qlo[ML * HDIM];
__device__ __nv_bfloat16 g_Khi[ML * HDIM];
__device__ __nv_bfloat16 g_Klo[ML * HDIM];
__device__ float         g_V[ML * HDIM];
__device__ float         g_colsum[ML];
__device__ float         g_diag[ML];

// ---------------- helpers --------------------------------------------------
__device__ __forceinline__ uint32_t smem_u32(const void* p) {
    uint32_t a;
    asm("{ .reg .u64 t; cvta.to.shared.u64 t, %1; cvt.u32.u64 %0, t; }"
        : "=r"(a) : "l"(p));
    return a;
}

__device__ __forceinline__ void cp16(uint32_t s, const void* g) {
    asm volatile("cp.async.cg.shared.global [%0], [%1], 16;" :: "r"(s), "l"(g));
}
#define CP_COMMIT() asm volatile("cp.async.commit_group;" ::: "memory")
#define CP_WAIT2()  asm volatile("cp.async.wait_group 2;" ::: "memory")
#define CP_WAIT1()  asm volatile("cp.async.wait_group 1;" ::: "memory")
#define CP_WAIT0()  asm volatile("cp.async.wait_group 0;" ::: "memory")

__device__ __forceinline__ void ldsm4(uint32_t* a, uint32_t addr) {
    asm volatile("ldmatrix.sync.aligned.m8n8.x4.shared.b16 {%0,%1,%2,%3}, [%4];"
                 : "=r"(a[0]), "=r"(a[1]), "=r"(a[2]), "=r"(a[3]) : "r"(addr));
}
__device__ __forceinline__ void ldsm2(uint32_t* b, uint32_t addr) {
    asm volatile("ldmatrix.sync.aligned.m8n8.x2.shared.b16 {%0,%1}, [%2];"
                 : "=r"(b[0]), "=r"(b[1]) : "r"(addr));
}
__device__ __forceinline__ void mma16816(float* d, const uint32_t* a, const uint32_t* b) {
    asm volatile(
        "mma.sync.aligned.m16n8k16.row.col.f32.bf16.bf16.f32 "
        "{%0,%1,%2,%3}, {%4,%5,%6,%7}, {%8,%9}, {%0,%1,%2,%3};"
        : "+f"(d[0]), "+f"(d[1]), "+f"(d[2]), "+f"(d[3])
        : "r"(a[0]), "r"(a[1]), "r"(a[2]), "r"(a[3]), "r"(b[0]), "r"(b[1]));
}

// ---------------- tiling constants -----------------------------------------
#define PITCH   80                    // bytes per smem row (32 bf16 + 16B pad)
#define TSZ     (128 * PITCH)         // one operand tile: 10240 B
#define STG3    (4 * TSZ)             // 3-term stage: Ah, Al, Bh, Bl = 40960 B
#define STG1    (2 * TSZ)             // 1-term stage: Ah, Bh       = 20480 B
#define DYNSMEM (2 * STG3)            // 81920 B (== 4 * STG1)

// ---------------------------------------------------------------------------
// run_tile3: 128x128 tile, split-bf16 (hi*hi + hi*lo + lo*hi), 2-stage pipe.
// ---------------------------------------------------------------------------
__device__ __forceinline__ void run_tile3(
    const __nv_bfloat16* __restrict__ Ah, const __nv_bfloat16* __restrict__ Al,
    const __nv_bfloat16* __restrict__ Bh, const __nv_bfloat16* __restrict__ Bl,
    int m0, int n0, int Kdim, char* sm, float (&acc)[4][4][4])
{
    const int tid  = threadIdx.x;
    const int wid  = tid >> 5, lane = tid & 31;
    const int wm   = wid >> 2, wn = wid & 3;
    const uint32_t sbase = smem_u32(sm);

    const int r  = tid >> 1, cg = tid & 1;
    const size_t ga = (size_t)(m0 + r) * Kdim + cg * 16;
    const size_t gb = (size_t)(n0 + r) * Kdim + cg * 16;
    const uint32_t soff = (uint32_t)(r * PITCH + cg * 32);

    const uint32_t aoff = (uint32_t)((wm * 64 + (lane & 15)) * PITCH + (lane >> 4) * 16);
    const uint32_t boff = (uint32_t)((wn * 32 + (lane & 7)) * PITCH + ((lane >> 3) & 1) * 16);

#define LOADC3(st, kc) do {                                                   \
    const uint32_t s0 = sbase + (uint32_t)(st) * STG3 + soff;                 \
    cp16(s0 + 0 * TSZ,      Ah + ga + (kc));                                  \
    cp16(s0 + 0 * TSZ + 16, Ah + ga + (kc) + 8);                              \
    cp16(s0 + 1 * TSZ,      Al + ga + (kc));                                  \
    cp16(s0 + 1 * TSZ + 16, Al + ga + (kc) + 8);                              \
    cp16(s0 + 2 * TSZ,      Bh + gb + (kc));                                  \
    cp16(s0 + 2 * TSZ + 16, Bh + gb + (kc) + 8);                              \
    cp16(s0 + 3 * TSZ,      Bl + gb + (kc));                                  \
    cp16(s0 + 3 * TSZ + 16, Bl + gb + (kc) + 8);                              \
    CP_COMMIT();                                                              \
} while (0)

    const int NC = Kdim / 32;
    LOADC3(0, 0);

#pragma unroll 1
    for (int c = 0; c < NC; c++) {
        if (c + 1 < NC) { LOADC3((c + 1) & 1, (c + 1) * 32); CP_WAIT1(); }
        else            { CP_WAIT0(); }
        __syncthreads();

        const uint32_t tb = sbase + (uint32_t)(c & 1) * STG3;
#pragma unroll
        for (int k16 = 0; k16 < 2; k16++) {
            uint32_t ah[4][4], al[4][4], bh[4][2], bl[4][2];
#pragma unroll
            for (int mi = 0; mi < 4; mi++) {
                ldsm4(ah[mi], tb + 0 * TSZ + aoff + mi * 16 * PITCH + k16 * 32);
                ldsm4(al[mi], tb + 1 * TSZ + aoff + mi * 16 * PITCH + k16 * 32);
            }
#pragma unroll
            for (int ni = 0; ni < 4; ni++) {
                ldsm2(bh[ni], tb + 2 * TSZ + boff + ni * 8 * PITCH + k16 * 32);
                ldsm2(bl[ni], tb + 3 * TSZ + boff + ni * 8 * PITCH + k16 * 32);
            }
#pragma unroll
            for (int mi = 0; mi < 4; mi++)
#pragma unroll
                for (int ni = 0; ni < 4; ni++) {
                    mma16816(acc[mi][ni], ah[mi], bh[ni]);
                    mma16816(acc[mi][ni], ah[mi], bl[ni]);
                    mma16816(acc[mi][ni], al[mi], bh[ni]);
                }
        }
        __syncthreads();
    }
#undef LOADC3
}

// ---------------------------------------------------------------------------
// run_tile1: 128x128 tile, hi-only (1 MMA term), 4-stage pipe, 1 sync/chunk.
// ---------------------------------------------------------------------------
__device__ __forceinline__ void run_tile1(
    const __nv_bfloat16* __restrict__ Ah, const __nv_bfloat16* __restrict__ Bh,
    int m0, int n0, int Kdim, char* sm, float (&acc)[4][4][4])
{
    const int tid  = threadIdx.x;
    const int wid  = tid >> 5, lane = tid & 31;
    const int wm   = wid >> 2, wn = wid & 3;
    const uint32_t sbase = smem_u32(sm);

    const int r  = tid >> 1, cg = tid & 1;
    const size_t ga = (size_t)(m0 + r) * Kdim + cg * 16;
    const size_t gb = (size_t)(n0 + r) * Kdim + cg * 16;
    const uint32_t soff = (uint32_t)(r * PITCH + cg * 32);

    const uint32_t aoff = (uint32_t)((wm * 64 + (lane & 15)) * PITCH + (lane >> 4) * 16);
    const uint32_t boff = (uint32_t)((wn * 32 + (lane & 7)) * PITCH + ((lane >> 3) & 1) * 16);

#define LOADC1(st, kc) do {                                                   \
    const uint32_t s0 = sbase + (uint32_t)(st) * STG1 + soff;                 \
    cp16(s0,            Ah + ga + (kc));                                      \
    cp16(s0 + 16,       Ah + ga + (kc) + 8);                                  \
    cp16(s0 + TSZ,      Bh + gb + (kc));                                      \
    cp16(s0 + TSZ + 16, Bh + gb + (kc) + 8);                                  \
    CP_COMMIT();                                                              \
} while (0)

    const int NC = Kdim / 32;
    LOADC1(0, 0);
    LOADC1(1, 32);
    LOADC1(2, 64);

#pragma unroll 1
    for (int c = 0; c < NC; c++) {
        CP_WAIT2();                 // chunk c resident
        __syncthreads();
        const uint32_t tb = sbase + (uint32_t)(c & 3) * STG1;
#pragma unroll
        for (int k16 = 0; k16 < 2; k16++) {
            uint32_t ah[4][4], bh[4][2];
#pragma unroll
            for (int mi = 0; mi < 4; mi++)
                ldsm4(ah[mi], tb + aoff + mi * 16 * PITCH + k16 * 32);
#pragma unroll
            for (int ni = 0; ni < 4; ni++)
                ldsm2(bh[ni], tb + TSZ + boff + ni * 8 * PITCH + k16 * 32);
#pragma unroll
            for (int mi = 0; mi < 4; mi++)
#pragma unroll
                for (int ni = 0; ni < 4; ni++)
                    mma16816(acc[mi][ni], ah[mi], bh[ni]);
        }
        if (c + 3 < NC) LOADC1((c + 3) & 3, (c + 3) * 32);
    }
#undef LOADC1
}

// ---------------------------------------------------------------------------
// Conversions fp32 -> (bf16 hi, bf16 lo)
// ---------------------------------------------------------------------------
__device__ __forceinline__ void split4(float4 v, __nv_bfloat162& h0, __nv_bfloat162& h1,
                                       __nv_bfloat162& l0, __nv_bfloat162& l1) {
    float f[4] = {v.x, v.y, v.z, v.w};
    __nv_bfloat16 h[4], l[4];
#pragma unroll
    for (int i = 0; i < 4; i++) {
        h[i] = __float2bfloat16(f[i]);
        l[i] = __float2bfloat16(f[i] - __bfloat162float(h[i]));
    }
    h0.x = h[0]; h0.y = h[1]; h1.x = h[2]; h1.y = h[3];
    l0.x = l[0]; l0.y = l[1]; l1.x = l[2]; l1.y = l[3];
}

__global__ void __launch_bounds__(256) convx_kernel(const float* __restrict__ X) {
    const size_t i = (size_t)blockIdx.x * 256 + threadIdx.x;
    float4 v = ((const float4*)X)[i];
    __nv_bfloat162 h0, h1, l0, l1;
    split4(v, h0, h1, l0, l1);
    ((__nv_bfloat162*)g_Xhi)[2 * i]     = h0;
    ((__nv_bfloat162*)g_Xhi)[2 * i + 1] = h1;
    ((__nv_bfloat162*)g_Xlo)[2 * i]     = l0;
    ((__nv_bfloat162*)g_Xlo)[2 * i + 1] = l1;
}

__global__ void __launch_bounds__(256) convw_kernel(
    const float* __restrict__ Wq, const float* __restrict__ Wk,
    const float* __restrict__ Wv)
{
    const float* W = blockIdx.z == 0 ? Wq : blockIdx.z == 1 ? Wk : Wv;
    const size_t i = (size_t)blockIdx.x * 256 + threadIdx.x;
    const size_t zoff = (size_t)blockIdx.z * (HDIM * (size_t)EDIM / 2);
    float4 v = ((const float4*)W)[i];
    __nv_bfloat162 h0, h1, l0, l1;
    split4(v, h0, h1, l0, l1);
    ((__nv_bfloat162*)g_Whi)[zoff + 2 * i]     = h0;
    ((__nv_bfloat162*)g_Whi)[zoff + 2 * i + 1] = h1;
    ((__nv_bfloat162*)g_Wlo)[zoff + 2 * i]     = l0;
    ((__nv_bfloat162*)g_Wlo)[zoff + 2 * i + 1] = l1;
}

// ---------------------------------------------------------------------------
// GEMM1: Q/K/V projections (3-term).  grid (8, 128, 3)
// ---------------------------------------------------------------------------
__global__ void __launch_bounds__(256) gemm1_kernel(
    const float* __restrict__ bq, const float* __restrict__ bk,
    const float* __restrict__ bv)
{
    extern __shared__ char dynsm[];
    const int z  = blockIdx.z;
    const int m0 = blockIdx.y * 128;
    const int n0 = blockIdx.x * 128;

    const __nv_bfloat16* Bh = g_Whi + (size_t)z * HDIM * EDIM;
    const __nv_bfloat16* Bl = g_Wlo + (size_t)z * HDIM * EDIM;

    float acc[4][4][4];
#pragma unroll
    for (int a = 0; a < 4; a++)
#pragma unroll
        for (int b = 0; b < 4; b++)
#pragma unroll
            for (int cc = 0; cc < 4; cc++) acc[a][b][cc] = 0.0f;

    run_tile3(g_Xhi, g_Xlo, Bh, Bl, m0, n0, EDIM, dynsm, acc);

    const float* bias = z == 0 ? bq : z == 1 ? bk : bv;
    __nv_bfloat16* oh = z == 0 ? g_Qhi : g_Khi;
    __nv_bfloat16* ol = z == 0 ? g_Qlo : g_Klo;

    const int tid = threadIdx.x;
    const int wid = tid >> 5, lane = tid & 31;
    const int wm = wid >> 2, wn = wid & 3;

#pragma unroll
    for (int mi = 0; mi < 4; mi++) {
        const int r0 = m0 + wm * 64 + mi * 16 + (lane >> 2);
#pragma unroll
        for (int ni = 0; ni < 4; ni++) {
            const int gc = n0 + wn * 32 + ni * 8 + 2 * (lane & 3);
            const float b0 = __ldg(&bias[gc]), b1 = __ldg(&bias[gc + 1]);
            const float v00 = acc[mi][ni][0] + b0, v01 = acc[mi][ni][1] + b1;
            const float v10 = acc[mi][ni][2] + b0, v11 = acc[mi][ni][3] + b1;
            if (z == 2) {
                *(float2*)(g_V + (size_t)r0 * HDIM + gc)       = make_float2(v00, v01);
                *(float2*)(g_V + (size_t)(r0 + 8) * HDIM + gc) = make_float2(v10, v11);
            } else {
                __nv_bfloat162 hh, ll;
                hh.x = __float2bfloat16(v00);
                hh.y = __float2bfloat16(v01);
                ll.x = __float2bfloat16(v00 - __bfloat162float(hh.x));
                ll.y = __float2bfloat16(v01 - __bfloat162float(hh.y));
                *(__nv_bfloat162*)(oh + (size_t)r0 * HDIM + gc) = hh;
                *(__nv_bfloat162*)(ol + (size_t)r0 * HDIM + gc) = ll;
                hh.x = __float2bfloat16(v10);
                hh.y = __float2bfloat16(v11);
                ll.x = __float2bfloat16(v10 - __bfloat162float(hh.x));
                ll.y = __float2bfloat16(v11 - __bfloat162float(hh.y));
                *(__nv_bfloat162*)(oh + (size_t)(r0 + 8) * HDIM + gc) = hh;
                *(__nv_bfloat162*)(ol + (size_t)(r0 + 8) * HDIM + gc) = ll;
            }
        }
    }
}

// ---------------------------------------------------------------------------
// GEMM2: scores, precision-stratified.
//   off-diagonal tile: hi-only 1-term (feeds colsum; error averages out)
//   diagonal tile:     full 3-term (feeds diag directly)
// grid (32, 32, 4)
// ---------------------------------------------------------------------------
__global__ void __launch_bounds__(256) gemm2_kernel()
{
    extern __shared__ char dynsm[];
    __shared__ float sred[128];

    const int bz = blockIdx.z;
    const int m0 = blockIdx.y * 128;
    const int n0 = blockIdx.x * 128;
    const int tid = threadIdx.x;
    const bool diagblk = (blockIdx.x == blockIdx.y);

    if (tid < 128) sred[tid] = 0.0f;

    const size_t bo = (size_t)bz * LSEQ * HDIM;
    float acc[4][4][4];
#pragma unroll
    for (int a = 0; a < 4; a++)
#pragma unroll
        for (int b = 0; b < 4; b++)
#pragma unroll
            for (int cc = 0; cc < 4; cc++) acc[a][b][cc] = 0.0f;

    if (diagblk)
        run_tile3(g_Qhi + bo, g_Qlo + bo, g_Khi + bo, g_Klo + bo,
                  m0, n0, HDIM, dynsm, acc);
    else
        run_tile1(g_Qhi + bo, g_Khi + bo, m0, n0, HDIM, dynsm, acc);

    const int wid = tid >> 5, lane = tid & 31;
    const int wm = wid >> 2, wn = wid & 3;
    const float sc = 0.015625f;   // 1/sqrt(4096)

    float2 csum[4];
#pragma unroll
    for (int ni = 0; ni < 4; ni++) csum[ni] = make_float2(0.0f, 0.0f);

#pragma unroll
    for (int mi = 0; mi < 4; mi++) {
        const int lr = wm * 64 + mi * 16 + (lane >> 2);
#pragma unroll
        for (int ni = 0; ni < 4; ni++) {
            const int lc = wn * 32 + ni * 8 + 2 * (lane & 3);
            const float e00 = __expf(acc[mi][ni][0] * sc);
            const float e01 = __expf(acc[mi][ni][1] * sc);
            const float e10 = __expf(acc[mi][ni][2] * sc);
            const float e11 = __expf(acc[mi][ni][3] * sc);
            csum[ni].x += e00 + e10;
            csum[ni].y += e01 + e11;
            if (diagblk) {
                if (lr == lc)         g_diag[(size_t)bz * LSEQ + m0 + lr] = e00;
                if (lr == lc + 1)     g_diag[(size_t)bz * LSEQ + m0 + lr] = e01;
                if (lr + 8 == lc)     g_diag[(size_t)bz * LSEQ + m0 + lr + 8] = e10;
                if (lr + 8 == lc + 1) g_diag[(size_t)bz * LSEQ + m0 + lr + 8] = e11;
            }
        }
    }

    __syncthreads();   // orders sred init vs atomics below

#pragma unroll
    for (int ni = 0; ni < 4; ni++) {
#pragma unroll
        for (int m = 4; m <= 16; m <<= 1) {
            csum[ni].x += __shfl_xor_sync(0xffffffffu, csum[ni].x, m);
            csum[ni].y += __shfl_xor_sync(0xffffffffu, csum[ni].y, m);
        }
        if (lane < 4) {
            atomicAdd(&sred[wn * 32 + ni * 8 + 2 * lane],     csum[ni].x);
            atomicAdd(&sred[wn * 32 + ni * 8 + 2 * lane + 1], csum[ni].y);
        }
    }

    __syncthreads();
    if (tid < 128)
        atomicAdd(&g_colsum[(size_t)bz * LSEQ + n0 + tid], sred[tid]);
}

// ---------------------------------------------------------------------------
__global__ void __launch_bounds__(256) finalize_kernel(float* __restrict__ out)
{
    const int row = blockIdx.x;
    const float scale = g_diag[row] / g_colsum[row];
    const float4* v = (const float4*)(g_V + (size_t)row * HDIM);
    float4* o = (float4*)(out + (size_t)row * HDIM);
    float4 x = v[threadIdx.x];
    x.x *= scale; x.y *= scale; x.z *= scale; x.w *= scale;
    o[threadIdx.x] = x;
}

__global__ void zero_kernel()
{
    const int i = blockIdx.x * 256 + threadIdx.x;
    if (i < ML) g_colsum[i] = 0.0f;
}

// ---------------------------------------------------------------------------
extern "C" void kernel_launch(void* const* d_in, const int* in_sizes, int n_in,
                              void* d_out, int out_size)
{
    (void)in_sizes; (void)n_in; (void)out_size;
    const float* X  = (const float*)d_in[0];
    const float* Wq = (const float*)d_in[1];
    const float* bq = (const float*)d_in[2];
    const float* Wk = (const float*)d_in[3];
    const float* bk = (const float*)d_in[4];
    const float* Wv = (const float*)d_in[5];
    const float* bv = (const float*)d_in[6];
    float* out = (float*)d_out;

    // Idempotent host-side attribute set (not a stream op; capture-safe).
    cudaFuncSetAttribute(gemm1_kernel, cudaFuncAttributeMaxDynamicSharedMemorySize, DYNSMEM);
    cudaFuncSetAttribute(gemm2_kernel, cudaFuncAttributeMaxDynamicSharedMemorySize, DYNSMEM);

    zero_kernel<<<(ML + 255) / 256, 256>>>();

    convx_kernel<<<(ML * EDIM / 4) / 256, 256>>>(X);
    dim3 gw((HDIM * EDIM / 4) / 256, 1, 3);
    convw_kernel<<<gw, 256>>>(Wq, Wk, Wv);

    dim3 g1(HDIM / 128, ML / 128, 3);
    gemm1_kernel<<<g1, 256, DYNSMEM>>>(bq, bk, bv);

    dim3 g2(LSEQ / 128, LSEQ / 128, NB);
    gemm2_kernel<<<g2, 256, DYNSMEM>>>();

    finalize_kernel<<<ML, 256>>>(out);
}

// round 7
// speedup vs baseline: 5.1918x; 1.1649x over previous
#include <cuda_runtime.h>
#include <cuda_bf16.h>
#include <math.h>
#include <stdint.h>

#define NB   4
#define LSEQ 4096
#define EDIM 1024
#define HDIM 1024
#define ML   (NB * LSEQ)      // 16384

// ---------------- scratch (static device arrays; no allocation APIs) -------
__device__ __nv_bfloat16 g_Xhi[ML * EDIM];          // 32 MB
__device__ __nv_bfloat16 g_Xlo[ML * EDIM];
__device__ __nv_bfloat16 g_Wvhi[HDIM * EDIM];       // 2 MB
__device__ __nv_bfloat16 g_Wvlo[HDIM * EDIM];
__device__ __nv_bfloat16 g_WqThi[EDIM * HDIM];      // Wq^T: [e][h]
__device__ __nv_bfloat16 g_WqTlo[EDIM * HDIM];
__device__ __nv_bfloat16 g_WkThi[EDIM * HDIM];
__device__ __nv_bfloat16 g_WkTlo[EDIM * HDIM];
__device__ __nv_bfloat16 g_Mhi[EDIM * EDIM];        // M^T stored [e'][e]
__device__ __nv_bfloat16 g_Mlo[EDIM * EDIM];
__device__ __nv_bfloat16 g_Qkhi[ML * EDIM];         // Qk = X*M^T
__device__ __nv_bfloat16 g_Qklo[ML * EDIM];
__device__ float         g_V[ML * HDIM];            // 64 MB
__device__ float         g_w1[EDIM];                // Wq^T * bk
__device__ float         g_w2[EDIM];                // Wk^T * bq
__device__ float         g_alpha[ML];               // X * w1
__device__ float         g_beta[ML];                // X * w2
__device__ float         g_c;                       // bq . bk
__device__ float         g_colsum[ML];
__device__ float         g_diag[ML];

// ---------------- helpers --------------------------------------------------
__device__ __forceinline__ uint32_t smem_u32(const void* p) {
    uint32_t a;
    asm("{ .reg .u64 t; cvta.to.shared.u64 t, %1; cvt.u32.u64 %0, t; }"
        : "=r"(a) : "l"(p));
    return a;
}

__device__ __forceinline__ void cp16(uint32_t s, const void* g) {
    asm volatile("cp.async.cg.shared.global [%0], [%1], 16;" :: "r"(s), "l"(g));
}
#define CP_COMMIT() asm volatile("cp.async.commit_group;" ::: "memory")
#define CP_WAIT2()  asm volatile("cp.async.wait_group 2;" ::: "memory")
#define CP_WAIT1()  asm volatile("cp.async.wait_group 1;" ::: "memory")
#define CP_WAIT0()  asm volatile("cp.async.wait_group 0;" ::: "memory")

__device__ __forceinline__ void ldsm4(uint32_t* a, uint32_t addr) {
    asm volatile("ldmatrix.sync.aligned.m8n8.x4.shared.b16 {%0,%1,%2,%3}, [%4];"
                 : "=r"(a[0]), "=r"(a[1]), "=r"(a[2]), "=r"(a[3]) : "r"(addr));
}
__device__ __forceinline__ void ldsm2(uint32_t* b, uint32_t addr) {
    asm volatile("ldmatrix.sync.aligned.m8n8.x2.shared.b16 {%0,%1}, [%2];"
                 : "=r"(b[0]), "=r"(b[1]) : "r"(addr));
}
__device__ __forceinline__ void mma16816(float* d, const uint32_t* a, const uint32_t* b) {
    asm volatile(
        "mma.sync.aligned.m16n8k16.row.col.f32.bf16.bf16.f32 "
        "{%0,%1,%2,%3}, {%4,%5,%6,%7}, {%8,%9}, {%0,%1,%2,%3};"
        : "+f"(d[0]), "+f"(d[1]), "+f"(d[2]), "+f"(d[3])
        : "r"(a[0]), "r"(a[1]), "r"(a[2]), "r"(a[3]), "r"(b[0]), "r"(b[1]));
}

// ---------------- tiling constants -----------------------------------------
#define PITCH   80                    // bytes per smem row (32 bf16 + 16B pad)
#define TSZ     (128 * PITCH)         // one operand tile: 10240 B
#define STG3    (4 * TSZ)             // 3-term stage: Ah, Al, Bh, Bl = 40960 B
#define STG1    (2 * TSZ)             // 1-term stage: Ah, Bh       = 20480 B
#define DYNSMEM (2 * STG3)            // 81920 B (== 4 * STG1)

// ---------------------------------------------------------------------------
// run_tile3: 128x128 tile, split-bf16 (hi*hi + hi*lo + lo*hi), 2-stage pipe.
// ---------------------------------------------------------------------------
__device__ __forceinline__ void run_tile3(
    const __nv_bfloat16* __restrict__ Ah, const __nv_bfloat16* __restrict__ Al,
    const __nv_bfloat16* __restrict__ Bh, const __nv_bfloat16* __restrict__ Bl,
    int m0, int n0, int Kdim, char* sm, float (&acc)[4][4][4])
{
    const int tid  = threadIdx.x;
    const int wid  = tid >> 5, lane = tid & 31;
    const int wm   = wid >> 2, wn = wid & 3;
    const uint32_t sbase = smem_u32(sm);

    const int r  = tid >> 1, cg = tid & 1;
    const size_t ga = (size_t)(m0 + r) * Kdim + cg * 16;
    const size_t gb = (size_t)(n0 + r) * Kdim + cg * 16;
    const uint32_t soff = (uint32_t)(r * PITCH + cg * 32);

    const uint32_t aoff = (uint32_t)((wm * 64 + (lane & 15)) * PITCH + (lane >> 4) * 16);
    const uint32_t boff = (uint32_t)((wn * 32 + (lane & 7)) * PITCH + ((lane >> 3) & 1) * 16);

#define LOADC3(st, kc) do {                                                   \
    const uint32_t s0 = sbase + (uint32_t)(st) * STG3 + soff;                 \
    cp16(s0 + 0 * TSZ,      Ah + ga + (kc));                                  \
    cp16(s0 + 0 * TSZ + 16, Ah + ga + (kc) + 8);                              \
    cp16(s0 + 1 * TSZ,      Al + ga + (kc));                                  \
    cp16(s0 + 1 * TSZ + 16, Al + ga + (kc) + 8);                              \
    cp16(s0 + 2 * TSZ,      Bh + gb + (kc));                                  \
    cp16(s0 + 2 * TSZ + 16, Bh + gb + (kc) + 8);                              \
    cp16(s0 + 3 * TSZ,      Bl + gb + (kc));                                  \
    cp16(s0 + 3 * TSZ + 16, Bl + gb + (kc) + 8);                              \
    CP_COMMIT();                                                              \
} while (0)

    const int NC = Kdim / 32;
    LOADC3(0, 0);

#pragma unroll 1
    for (int c = 0; c < NC; c++) {
        if (c + 1 < NC) { LOADC3((c + 1) & 1, (c + 1) * 32); CP_WAIT1(); }
        else            { CP_WAIT0(); }
        __syncthreads();

        const uint32_t tb = sbase + (uint32_t)(c & 1) * STG3;
#pragma unroll
        for (int k16 = 0; k16 < 2; k16++) {
            uint32_t ah[4][4], al[4][4], bh[4][2], bl[4][2];
#pragma unroll
            for (int mi = 0; mi < 4; mi++) {
                ldsm4(ah[mi], tb + 0 * TSZ + aoff + mi * 16 * PITCH + k16 * 32);
                ldsm4(al[mi], tb + 1 * TSZ + aoff + mi * 16 * PITCH + k16 * 32);
            }
#pragma unroll
            for (int ni = 0; ni < 4; ni++) {
                ldsm2(bh[ni], tb + 2 * TSZ + boff + ni * 8 * PITCH + k16 * 32);
                ldsm2(bl[ni], tb + 3 * TSZ + boff + ni * 8 * PITCH + k16 * 32);
            }
#pragma unroll
            for (int mi = 0; mi < 4; mi++)
#pragma unroll
                for (int ni = 0; ni < 4; ni++) {
                    mma16816(acc[mi][ni], ah[mi], bh[ni]);
                    mma16816(acc[mi][ni], ah[mi], bl[ni]);
                    mma16816(acc[mi][ni], al[mi], bh[ni]);
                }
        }
        __syncthreads();
    }
#undef LOADC3
}

// ---------------------------------------------------------------------------
// run_tile1: 128x128 tile, hi-only (1 MMA term), 4-stage pipe, 1 sync/chunk.
// ---------------------------------------------------------------------------
__device__ __forceinline__ void run_tile1(
    const __nv_bfloat16* __restrict__ Ah, const __nv_bfloat16* __restrict__ Bh,
    int m0, int n0, int Kdim, char* sm, float (&acc)[4][4][4])
{
    const int tid  = threadIdx.x;
    const int wid  = tid >> 5, lane = tid & 31;
    const int wm   = wid >> 2, wn = wid & 3;
    const uint32_t sbase = smem_u32(sm);

    const int r  = tid >> 1, cg = tid & 1;
    const size_t ga = (size_t)(m0 + r) * Kdim + cg * 16;
    const size_t gb = (size_t)(n0 + r) * Kdim + cg * 16;
    const uint32_t soff = (uint32_t)(r * PITCH + cg * 32);

    const uint32_t aoff = (uint32_t)((wm * 64 + (lane & 15)) * PITCH + (lane >> 4) * 16);
    const uint32_t boff = (uint32_t)((wn * 32 + (lane & 7)) * PITCH + ((lane >> 3) & 1) * 16);

#define LOADC1(st, kc) do {                                                   \
    const uint32_t s0 = sbase + (uint32_t)(st) * STG1 + soff;                 \
    cp16(s0,            Ah + ga + (kc));                                      \
    cp16(s0 + 16,       Ah + ga + (kc) + 8);                                  \
    cp16(s0 + TSZ,      Bh + gb + (kc));                                      \
    cp16(s0 + TSZ + 16, Bh + gb + (kc) + 8);                                  \
    CP_COMMIT();                                                              \
} while (0)

    const int NC = Kdim / 32;
    LOADC1(0, 0);
    LOADC1(1, 32);
    LOADC1(2, 64);

#pragma unroll 1
    for (int c = 0; c < NC; c++) {
        CP_WAIT2();
        __syncthreads();
        const uint32_t tb = sbase + (uint32_t)(c & 3) * STG1;
#pragma unroll
        for (int k16 = 0; k16 < 2; k16++) {
            uint32_t ah[4][4], bh[4][2];
#pragma unroll
            for (int mi = 0; mi < 4; mi++)
                ldsm4(ah[mi], tb + aoff + mi * 16 * PITCH + k16 * 32);
#pragma unroll
            for (int ni = 0; ni < 4; ni++)
                ldsm2(bh[ni], tb + TSZ + boff + ni * 8 * PITCH + k16 * 32);
#pragma unroll
            for (int mi = 0; mi < 4; mi++)
#pragma unroll
                for (int ni = 0; ni < 4; ni++)
                    mma16816(acc[mi][ni], ah[mi], bh[ni]);
        }
        if (c + 3 < NC) LOADC1((c + 3) & 3, (c + 3) * 32);
    }
#undef LOADC1
}

// ---------------------------------------------------------------------------
// Conversions / transposes
// ---------------------------------------------------------------------------
__device__ __forceinline__ void split4(float4 v, __nv_bfloat162& h0, __nv_bfloat162& h1,
                                       __nv_bfloat162& l0, __nv_bfloat162& l1) {
    float f[4] = {v.x, v.y, v.z, v.w};
    __nv_bfloat16 h[4], l[4];
#pragma unroll
    for (int i = 0; i < 4; i++) {
        h[i] = __float2bfloat16(f[i]);
        l[i] = __float2bfloat16(f[i] - __bfloat162float(h[i]));
    }
    h0.x = h[0]; h0.y = h[1]; h1.x = h[2]; h1.y = h[3];
    l0.x = l[0]; l0.y = l[1]; l1.x = l[2]; l1.y = l[3];
}

__global__ void __launch_bounds__(256) convx_kernel(const float* __restrict__ X) {
    const size_t i = (size_t)blockIdx.x * 256 + threadIdx.x;
    float4 v = ((const float4*)X)[i];
    __nv_bfloat162 h0, h1, l0, l1;
    split4(v, h0, h1, l0, l1);
    ((__nv_bfloat162*)g_Xhi)[2 * i]     = h0;
    ((__nv_bfloat162*)g_Xhi)[2 * i + 1] = h1;
    ((__nv_bfloat162*)g_Xlo)[2 * i]     = l0;
    ((__nv_bfloat162*)g_Xlo)[2 * i + 1] = l1;
}

__global__ void __launch_bounds__(256) convv_kernel(const float* __restrict__ Wv) {
    const size_t i = (size_t)blockIdx.x * 256 + threadIdx.x;
    float4 v = ((const float4*)Wv)[i];
    __nv_bfloat162 h0, h1, l0, l1;
    split4(v, h0, h1, l0, l1);
    ((__nv_bfloat162*)g_Wvhi)[2 * i]     = h0;
    ((__nv_bfloat162*)g_Wvhi)[2 * i + 1] = h1;
    ((__nv_bfloat162*)g_Wvlo)[2 * i]     = l0;
    ((__nv_bfloat162*)g_Wvlo)[2 * i + 1] = l1;
}

// Transposed split copies of Wq, Wk: WT[e][h] = W[h][e], bf16 hi/lo.
__global__ void __launch_bounds__(256) transw_kernel(
    const float* __restrict__ Wq, const float* __restrict__ Wk)
{
    __shared__ float t[32][33];
    const int z = blockIdx.z;
    const float* W = z ? Wk : Wq;
    __nv_bfloat16* Th = z ? g_WkThi : g_WqThi;
    __nv_bfloat16* Tl = z ? g_WkTlo : g_WqTlo;
    const int e0 = blockIdx.x * 32, h0 = blockIdx.y * 32;
    const int tx = threadIdx.x & 31, ty = threadIdx.x >> 5;  // 32 x 8

#pragma unroll
    for (int i = ty; i < 32; i += 8)
        t[i][tx] = W[(size_t)(h0 + i) * EDIM + e0 + tx];
    __syncthreads();
#pragma unroll
    for (int i = ty; i < 32; i += 8) {
        float v = t[tx][i];                 // = W[h0+tx][e0+i]
        __nv_bfloat16 h = __float2bfloat16(v);
        __nv_bfloat16 l = __float2bfloat16(v - __bfloat162float(h));
        Th[(size_t)(e0 + i) * HDIM + h0 + tx] = h;
        Tl[(size_t)(e0 + i) * HDIM + h0 + tx] = l;
    }
}

// w1[e] = sum_h Wq[h,e]*bk[h],  w2[e] = sum_h Wk[h,e]*bq[h]
__global__ void __launch_bounds__(256) biasw_kernel(
    const float* __restrict__ bq, const float* __restrict__ bk)
{
    __shared__ float red[8];
    const int e = blockIdx.x, z = blockIdx.y;
    const __nv_bfloat16* Th = z ? g_WkThi : g_WqThi;
    const __nv_bfloat16* Tl = z ? g_WkTlo : g_WqTlo;
    const float* b = z ? bq : bk;
    float s = 0.0f;
    for (int h = threadIdx.x; h < HDIM; h += 256)
        s += (__bfloat162float(Th[(size_t)e * HDIM + h]) +
              __bfloat162float(Tl[(size_t)e * HDIM + h])) * b[h];
#pragma unroll
    for (int m = 16; m >= 1; m >>= 1) s += __shfl_xor_sync(0xffffffffu, s, m);
    if ((threadIdx.x & 31) == 0) red[threadIdx.x >> 5] = s;
    __syncthreads();
    if (threadIdx.x == 0) {
        float t = 0.0f;
#pragma unroll
        for (int i = 0; i < 8; i++) t += red[i];
        (z ? g_w2 : g_w1)[e] = t;
    }
}

__global__ void cscalar_kernel(const float* __restrict__ bq,
                               const float* __restrict__ bk)
{
    __shared__ float red[8];
    float s = 0.0f;
    for (int h = threadIdx.x; h < HDIM; h += 256) s += bq[h] * bk[h];
#pragma unroll
    for (int m = 16; m >= 1; m >>= 1) s += __shfl_xor_sync(0xffffffffu, s, m);
    if ((threadIdx.x & 31) == 0) red[threadIdx.x >> 5] = s;
    __syncthreads();
    if (threadIdx.x == 0) {
        float t = 0.0f;
#pragma unroll
        for (int i = 0; i < 8; i++) t += red[i];
        g_c = t;
    }
}

// alpha[l] = X[l].w1, beta[l] = X[l].w2  (exact fp32 inputs)
__global__ void __launch_bounds__(256) alphabeta_kernel(const float* __restrict__ X)
{
    __shared__ float reda[8], redb[8];
    const int l = blockIdx.x;
    float sa = 0.0f, sb = 0.0f;
    for (int e = threadIdx.x; e < EDIM; e += 256) {
        float x = X[(size_t)l * EDIM + e];
        sa += x * g_w1[e];
        sb += x * g_w2[e];
    }
#pragma unroll
    for (int m = 16; m >= 1; m >>= 1) {
        sa += __shfl_xor_sync(0xffffffffu, sa, m);
        sb += __shfl_xor_sync(0xffffffffu, sb, m);
    }
    if ((threadIdx.x & 31) == 0) { reda[threadIdx.x >> 5] = sa; redb[threadIdx.x >> 5] = sb; }
    __syncthreads();
    if (threadIdx.x == 0) {
        float ta = 0.0f, tb = 0.0f;
#pragma unroll
        for (int i = 0; i < 8; i++) { ta += reda[i]; tb += redb[i]; }
        g_alpha[l] = ta;
        g_beta[l]  = tb;
    }
}

// ---------------------------------------------------------------------------
// mgemm: Mt[e'][e] = sum_h Wk[h,e']*Wq[h,e]  (3-term).  grid (8, 8)
// ---------------------------------------------------------------------------
__global__ void __launch_bounds__(256) mgemm_kernel()
{
    extern __shared__ char dynsm[];
    const int m0 = blockIdx.y * 128;   // e'
    const int n0 = blockIdx.x * 128;   // e

    float acc[4][4][4];
#pragma unroll
    for (int a = 0; a < 4; a++)
#pragma unroll
        for (int b = 0; b < 4; b++)
#pragma unroll
            for (int cc = 0; cc < 4; cc++) acc[a][b][cc] = 0.0f;

    run_tile3(g_WkThi, g_WkTlo, g_WqThi, g_WqTlo, m0, n0, HDIM, dynsm, acc);

    const int tid = threadIdx.x;
    const int wid = tid >> 5, lane = tid & 31;
    const int wm = wid >> 2, wn = wid & 3;

#pragma unroll
    for (int mi = 0; mi < 4; mi++) {
        const int r0 = m0 + wm * 64 + mi * 16 + (lane >> 2);
#pragma unroll
        for (int ni = 0; ni < 4; ni++) {
            const int gc = n0 + wn * 32 + ni * 8 + 2 * (lane & 3);
#pragma unroll
            for (int hh = 0; hh < 2; hh++) {
                const int rr = r0 + hh * 8;
                const float v0 = acc[mi][ni][2 * hh], v1 = acc[mi][ni][2 * hh + 1];
                __nv_bfloat162 h2, l2;
                h2.x = __float2bfloat16(v0);
                h2.y = __float2bfloat16(v1);
                l2.x = __float2bfloat16(v0 - __bfloat162float(h2.x));
                l2.y = __float2bfloat16(v1 - __bfloat162float(h2.y));
                *(__nv_bfloat162*)(g_Mhi + (size_t)rr * EDIM + gc) = h2;
                *(__nv_bfloat162*)(g_Mlo + (size_t)rr * EDIM + gc) = l2;
            }
        }
    }
}

// ---------------------------------------------------------------------------
// GEMM1: z=0: Qk = X*M^T (split bf16 out);  z=1: V = X*Wv^T + bv (fp32 out)
// grid (8, 128, 2)
// ---------------------------------------------------------------------------
__global__ void __launch_bounds__(256) gemm1_kernel(const float* __restrict__ bv)
{
    extern __shared__ char dynsm[];
    const int z  = blockIdx.z;
    const int m0 = blockIdx.y * 128;
    const int n0 = blockIdx.x * 128;

    const __nv_bfloat16* Bh = z ? g_Wvhi : g_Mhi;
    const __nv_bfloat16* Bl = z ? g_Wvlo : g_Mlo;

    float acc[4][4][4];
#pragma unroll
    for (int a = 0; a < 4; a++)
#pragma unroll
        for (int b = 0; b < 4; b++)
#pragma unroll
            for (int cc = 0; cc < 4; cc++) acc[a][b][cc] = 0.0f;

    run_tile3(g_Xhi, g_Xlo, Bh, Bl, m0, n0, EDIM, dynsm, acc);

    const int tid = threadIdx.x;
    const int wid = tid >> 5, lane = tid & 31;
    const int wm = wid >> 2, wn = wid & 3;

#pragma unroll
    for (int mi = 0; mi < 4; mi++) {
        const int r0 = m0 + wm * 64 + mi * 16 + (lane >> 2);
#pragma unroll
        for (int ni = 0; ni < 4; ni++) {
            const int gc = n0 + wn * 32 + ni * 8 + 2 * (lane & 3);
            if (z == 1) {
                const float b0 = __ldg(&bv[gc]), b1 = __ldg(&bv[gc + 1]);
                *(float2*)(g_V + (size_t)r0 * HDIM + gc) =
                    make_float2(acc[mi][ni][0] + b0, acc[mi][ni][1] + b1);
                *(float2*)(g_V + (size_t)(r0 + 8) * HDIM + gc) =
                    make_float2(acc[mi][ni][2] + b0, acc[mi][ni][3] + b1);
            } else {
#pragma unroll
                for (int hh = 0; hh < 2; hh++) {
                    const int rr = r0 + hh * 8;
                    const float v0 = acc[mi][ni][2 * hh], v1 = acc[mi][ni][2 * hh + 1];
                    __nv_bfloat162 h2, l2;
                    h2.x = __float2bfloat16(v0);
                    h2.y = __float2bfloat16(v1);
                    l2.x = __float2bfloat16(v0 - __bfloat162float(h2.x));
                    l2.y = __float2bfloat16(v1 - __bfloat162float(h2.y));
                    *(__nv_bfloat162*)(g_Qkhi + (size_t)rr * EDIM + gc) = h2;
                    *(__nv_bfloat162*)(g_Qklo + (size_t)rr * EDIM + gc) = l2;
                }
            }
        }
    }
}

// ---------------------------------------------------------------------------
// Scores epilogue helper: exp + colsum (+ optional diag), with alpha/beta/c.
// ---------------------------------------------------------------------------
__device__ __forceinline__ void scores_epilogue(
    float (&acc)[4][4][4], int bz, int m0, int n0, bool diagblk)
{
    __shared__ float sred[128];
    const int tid = threadIdx.x;
    const int wid = tid >> 5, lane = tid & 31;
    const int wm = wid >> 2, wn = wid & 3;
    const float sc = 0.015625f;   // 1/sqrt(4096)
    const float cc = g_c;

    if (tid < 128) sred[tid] = 0.0f;

    float2 csum[4];
#pragma unroll
    for (int ni = 0; ni < 4; ni++) csum[ni] = make_float2(0.0f, 0.0f);

#pragma unroll
    for (int mi = 0; mi < 4; mi++) {
        const int lr = wm * 64 + mi * 16 + (lane >> 2);
        const float a0 = g_alpha[(size_t)bz * LSEQ + m0 + lr];
        const float a1 = g_alpha[(size_t)bz * LSEQ + m0 + lr + 8];
#pragma unroll
        for (int ni = 0; ni < 4; ni++) {
            const int lc = wn * 32 + ni * 8 + 2 * (lane & 3);
            const float b0 = g_beta[(size_t)bz * LSEQ + n0 + lc];
            const float b1 = g_beta[(size_t)bz * LSEQ + n0 + lc + 1];
            const float e00 = __expf((acc[mi][ni][0] + a0 + b0 + cc) * sc);
            const float e01 = __expf((acc[mi][ni][1] + a0 + b1 + cc) * sc);
            const float e10 = __expf((acc[mi][ni][2] + a1 + b0 + cc) * sc);
            const float e11 = __expf((acc[mi][ni][3] + a1 + b1 + cc) * sc);
            csum[ni].x += e00 + e10;
            csum[ni].y += e01 + e11;
            if (diagblk) {
                if (lr == lc)         g_diag[(size_t)bz * LSEQ + m0 + lr] = e00;
                if (lr == lc + 1)     g_diag[(size_t)bz * LSEQ + m0 + lr] = e01;
                if (lr + 8 == lc)     g_diag[(size_t)bz * LSEQ + m0 + lr + 8] = e10;
                if (lr + 8 == lc + 1) g_diag[(size_t)bz * LSEQ + m0 + lr + 8] = e11;
            }
        }
    }

    __syncthreads();   // sred init visible

#pragma unroll
    for (int ni = 0; ni < 4; ni++) {
#pragma unroll
        for (int m = 4; m <= 16; m <<= 1) {
            csum[ni].x += __shfl_xor_sync(0xffffffffu, csum[ni].x, m);
            csum[ni].y += __shfl_xor_sync(0xffffffffu, csum[ni].y, m);
        }
        if (lane < 4) {
            atomicAdd(&sred[wn * 32 + ni * 8 + 2 * lane],     csum[ni].x);
            atomicAdd(&sred[wn * 32 + ni * 8 + 2 * lane + 1], csum[ni].y);
        }
    }

    __syncthreads();
    if (tid < 128)
        atomicAdd(&g_colsum[(size_t)bz * LSEQ + n0 + tid], sred[tid]);
}

// ---------------------------------------------------------------------------
// GEMM2 off-diagonal: S = Qkhi * Xhi^T (1 MMA term).  grid (32, 32, NB)
// ---------------------------------------------------------------------------
__global__ void __launch_bounds__(256) gemm2_off_kernel()
{
    if (blockIdx.x == blockIdx.y) return;   // diag handled separately
    extern __shared__ char dynsm[];

    const int bz = blockIdx.z;
    const int m0 = blockIdx.y * 128;
    const int n0 = blockIdx.x * 128;
    const size_t bo = (size_t)bz * LSEQ * EDIM;

    float acc[4][4][4];
#pragma unroll
    for (int a = 0; a < 4; a++)
#pragma unroll
        for (int b = 0; b < 4; b++)
#pragma unroll
            for (int cc = 0; cc < 4; cc++) acc[a][b][cc] = 0.0f;

    run_tile1(g_Qkhi + bo, g_Xhi + bo, m0, n0, EDIM, dynsm, acc);
    scores_epilogue(acc, bz, m0, n0, false);
}

// ---------------------------------------------------------------------------
// GEMM2 diagonal: 3-term split, diag extraction.  grid (32, NB)
// ---------------------------------------------------------------------------
__global__ void __launch_bounds__(256) gemm2_diag_kernel()
{
    extern __shared__ char dynsm[];
    const int bz = blockIdx.y;
    const int m0 = blockIdx.x * 128;
    const size_t bo = (size_t)bz * LSEQ * EDIM;

    float acc[4][4][4];
#pragma unroll
    for (int a = 0; a < 4; a++)
#pragma unroll
        for (int b = 0; b < 4; b++)
#pragma unroll
            for (int cc = 0; cc < 4; cc++) acc[a][b][cc] = 0.0f;

    run_tile3(g_Qkhi + bo, g_Qklo + bo, g_Xhi + bo, g_Xlo + bo,
              m0, m0, EDIM, dynsm, acc);
    scores_epilogue(acc, bz, m0, m0, true);
}

// ---------------------------------------------------------------------------
__global__ void __launch_bounds__(256) finalize_kernel(float* __restrict__ out)
{
    const int row = blockIdx.x;
    const float scale = g_diag[row] / g_colsum[row];
    const float4* v = (const float4*)(g_V + (size_t)row * HDIM);
    float4* o = (float4*)(out + (size_t)row * HDIM);
    float4 x = v[threadIdx.x];
    x.x *= scale; x.y *= scale; x.z *= scale; x.w *= scale;
    o[threadIdx.x] = x;
}

__global__ void zero_kernel()
{
    const int i = blockIdx.x * 256 + threadIdx.x;
    if (i < ML) g_colsum[i] = 0.0f;
}

// ---------------------------------------------------------------------------
extern "C" void kernel_launch(void* const* d_in, const int* in_sizes, int n_in,
                              void* d_out, int out_size)
{
    (void)in_sizes; (void)n_in; (void)out_size;
    const float* X  = (const float*)d_in[0];
    const float* Wq = (const float*)d_in[1];
    const float* bq = (const float*)d_in[2];
    const float* Wk = (const float*)d_in[3];
    const float* bk = (const float*)d_in[4];
    const float* Wv = (const float*)d_in[5];
    const float* bv = (const float*)d_in[6];
    float* out = (float*)d_out;

    cudaFuncSetAttribute(mgemm_kernel,      cudaFuncAttributeMaxDynamicSharedMemorySize, DYNSMEM);
    cudaFuncSetAttribute(gemm1_kernel,      cudaFuncAttributeMaxDynamicSharedMemorySize, DYNSMEM);
    cudaFuncSetAttribute(gemm2_off_kernel,  cudaFuncAttributeMaxDynamicSharedMemorySize, DYNSMEM);
    cudaFuncSetAttribute(gemm2_diag_kernel, cudaFuncAttributeMaxDynamicSharedMemorySize, DYNSMEM);

    zero_kernel<<<(ML + 255) / 256, 256>>>();

    convx_kernel<<<(ML * EDIM / 4) / 256, 256>>>(X);
    convv_kernel<<<(HDIM * EDIM / 4) / 256, 256>>>(Wv);

    dim3 gt(EDIM / 32, HDIM / 32, 2);
    transw_kernel<<<gt, 256>>>(Wq, Wk);

    dim3 gb(EDIM, 2);
    biasw_kernel<<<gb, 256>>>(bq, bk);
    cscalar_kernel<<<1, 256>>>(bq, bk);

    dim3 gm(EDIM / 128, EDIM / 128);
    mgemm_kernel<<<gm, 256, DYNSMEM>>>();

    alphabeta_kernel<<<ML, 256>>>(X);

    dim3 g1(EDIM / 128, ML / 128, 2);
    gemm1_kernel<<<g1, 256, DYNSMEM>>>(bv);

    dim3 g2(LSEQ / 128, LSEQ / 128, NB);
    gemm2_off_kernel<<<g2, 256, DYNSMEM>>>();

    dim3 g2d(LSEQ / 128, NB);
    gemm2_diag_kernel<<<g2d, 256, DYNSMEM>>>();

    finalize_kernel<<<ML, 256>>>(out);
}

// round 8
// speedup vs baseline: 5.2228x; 1.0060x over previous
#include <cuda_runtime.h>
#include <cuda_bf16.h>
#include <math.h>
#include <stdint.h>

#define NB   4
#define LSEQ 4096
#define EDIM 1024
#define HDIM 1024
#define ML   (NB * LSEQ)      // 16384

// ---------------- scratch (static device arrays; no allocation APIs) -------
__device__ __nv_bfloat16 g_Xhi[ML * EDIM];          // 32 MB
__device__ __nv_bfloat16 g_Xlo[ML * EDIM];
__device__ __nv_bfloat16 g_Wvhi[HDIM * EDIM];       // 2 MB
__device__ __nv_bfloat16 g_Wvlo[HDIM * EDIM];
__device__ __nv_bfloat16 g_WqThi[EDIM * HDIM];      // Wq^T: [e][h]
__device__ __nv_bfloat16 g_WqTlo[EDIM * HDIM];
__device__ __nv_bfloat16 g_WkThi[EDIM * HDIM];
__device__ __nv_bfloat16 g_WkTlo[EDIM * HDIM];
__device__ __nv_bfloat16 g_Mhi[EDIM * EDIM];        // M^T stored [e'][e]
__device__ __nv_bfloat16 g_Mlo[EDIM * EDIM];
__device__ __nv_bfloat16 g_Qkhi[ML * EDIM];         // Qk = X*M^T
__device__ __nv_bfloat16 g_Qklo[ML * EDIM];
__device__ float         g_V[ML * HDIM];            // 64 MB
__device__ float         g_w1[EDIM];                // Wq^T * bk
__device__ float         g_w2[EDIM];                // Wk^T * bq
__device__ float         g_alpha[ML];               // X * w1
__device__ float         g_beta[ML];                // X * w2
__device__ float         g_c;                       // bq . bk
__device__ float         g_colsum[ML];
__device__ float         g_diag[ML];

// ---------------- helpers --------------------------------------------------
__device__ __forceinline__ uint32_t smem_u32(const void* p) {
    uint32_t a;
    asm("{ .reg .u64 t; cvta.to.shared.u64 t, %1; cvt.u32.u64 %0, t; }"
        : "=r"(a) : "l"(p));
    return a;
}

__device__ __forceinline__ void cp16(uint32_t s, const void* g) {
    asm volatile("cp.async.cg.shared.global [%0], [%1], 16;" :: "r"(s), "l"(g));
}
#define CP_COMMIT() asm volatile("cp.async.commit_group;" ::: "memory")
#define CP_WAIT2()  asm volatile("cp.async.wait_group 2;" ::: "memory")
#define CP_WAIT1()  asm volatile("cp.async.wait_group 1;" ::: "memory")
#define CP_WAIT0()  asm volatile("cp.async.wait_group 0;" ::: "memory")

__device__ __forceinline__ void ldsm4(uint32_t* a, uint32_t addr) {
    asm volatile("ldmatrix.sync.aligned.m8n8.x4.shared.b16 {%0,%1,%2,%3}, [%4];"
                 : "=r"(a[0]), "=r"(a[1]), "=r"(a[2]), "=r"(a[3]) : "r"(addr));
}
__device__ __forceinline__ void ldsm2(uint32_t* b, uint32_t addr) {
    asm volatile("ldmatrix.sync.aligned.m8n8.x2.shared.b16 {%0,%1}, [%2];"
                 : "=r"(b[0]), "=r"(b[1]) : "r"(addr));
}
__device__ __forceinline__ void mma16816(float* d, const uint32_t* a, const uint32_t* b) {
    asm volatile(
        "mma.sync.aligned.m16n8k16.row.col.f32.bf16.bf16.f32 "
        "{%0,%1,%2,%3}, {%4,%5,%6,%7}, {%8,%9}, {%0,%1,%2,%3};"
        : "+f"(d[0]), "+f"(d[1]), "+f"(d[2]), "+f"(d[3])
        : "r"(a[0]), "r"(a[1]), "r"(a[2]), "r"(a[3]), "r"(b[0]), "r"(b[1]));
}

// ---------------- tiling constants -----------------------------------------
#define PITCH   80                    // bytes per smem row (32 bf16 + 16B pad)
#define TSZ     (128 * PITCH)         // one operand tile: 10240 B
#define STG3    (4 * TSZ)             // 3-term stage: Ah, Al, Bh, Bl = 40960 B
#define STG1    (2 * TSZ)             // 1-term stage: Ah, Bh       = 20480 B
#define DYNSMEM (2 * STG3)            // 81920 B (== 4 * STG1); 2 CTAs = 160 KB/SM

// ---------------------------------------------------------------------------
// run_tile3: 128x128 tile, split-bf16 (hi*hi + hi*lo + lo*hi), 2-stage pipe.
// ---------------------------------------------------------------------------
__device__ __forceinline__ void run_tile3(
    const __nv_bfloat16* __restrict__ Ah, const __nv_bfloat16* __restrict__ Al,
    const __nv_bfloat16* __restrict__ Bh, const __nv_bfloat16* __restrict__ Bl,
    int m0, int n0, int Kdim, char* sm, float (&acc)[4][4][4])
{
    const int tid  = threadIdx.x;
    const int wid  = tid >> 5, lane = tid & 31;
    const int wm   = wid >> 2, wn = wid & 3;
    const uint32_t sbase = smem_u32(sm);

    const int r  = tid >> 1, cg = tid & 1;
    const size_t ga = (size_t)(m0 + r) * Kdim + cg * 16;
    const size_t gb = (size_t)(n0 + r) * Kdim + cg * 16;
    const uint32_t soff = (uint32_t)(r * PITCH + cg * 32);

    const uint32_t aoff = (uint32_t)((wm * 64 + (lane & 15)) * PITCH + (lane >> 4) * 16);
    const uint32_t boff = (uint32_t)((wn * 32 + (lane & 7)) * PITCH + ((lane >> 3) & 1) * 16);

#define LOADC3(st, kc) do {                                                   \
    const uint32_t s0 = sbase + (uint32_t)(st) * STG3 + soff;                 \
    cp16(s0 + 0 * TSZ,      Ah + ga + (kc));                                  \
    cp16(s0 + 0 * TSZ + 16, Ah + ga + (kc) + 8);                              \
    cp16(s0 + 1 * TSZ,      Al + ga + (kc));                                  \
    cp16(s0 + 1 * TSZ + 16, Al + ga + (kc) + 8);                              \
    cp16(s0 + 2 * TSZ,      Bh + gb + (kc));                                  \
    cp16(s0 + 2 * TSZ + 16, Bh + gb + (kc) + 8);                              \
    cp16(s0 + 3 * TSZ,      Bl + gb + (kc));                                  \
    cp16(s0 + 3 * TSZ + 16, Bl + gb + (kc) + 8);                              \
    CP_COMMIT();                                                              \
} while (0)

    const int NC = Kdim / 32;
    LOADC3(0, 0);

#pragma unroll 1
    for (int c = 0; c < NC; c++) {
        if (c + 1 < NC) { LOADC3((c + 1) & 1, (c + 1) * 32); CP_WAIT1(); }
        else            { CP_WAIT0(); }
        __syncthreads();

        const uint32_t tb = sbase + (uint32_t)(c & 1) * STG3;
#pragma unroll
        for (int k16 = 0; k16 < 2; k16++) {
            uint32_t ah[4][4], al[4][4], bh[4][2], bl[4][2];
#pragma unroll
            for (int mi = 0; mi < 4; mi++) {
                ldsm4(ah[mi], tb + 0 * TSZ + aoff + mi * 16 * PITCH + k16 * 32);
                ldsm4(al[mi], tb + 1 * TSZ + aoff + mi * 16 * PITCH + k16 * 32);
            }
#pragma unroll
            for (int ni = 0; ni < 4; ni++) {
                ldsm2(bh[ni], tb + 2 * TSZ + boff + ni * 8 * PITCH + k16 * 32);
                ldsm2(bl[ni], tb + 3 * TSZ + boff + ni * 8 * PITCH + k16 * 32);
            }
#pragma unroll
            for (int mi = 0; mi < 4; mi++)
#pragma unroll
                for (int ni = 0; ni < 4; ni++) {
                    mma16816(acc[mi][ni], ah[mi], bh[ni]);
                    mma16816(acc[mi][ni], ah[mi], bl[ni]);
                    mma16816(acc[mi][ni], al[mi], bh[ni]);
                }
        }
        __syncthreads();
    }
#undef LOADC3
}

// ---------------------------------------------------------------------------
// run_tile1: 128x128 tile, hi-only (1 MMA term), 4-stage pipe, 1 sync/chunk.
// ---------------------------------------------------------------------------
__device__ __forceinline__ void run_tile1(
    const __nv_bfloat16* __restrict__ Ah, const __nv_bfloat16* __restrict__ Bh,
    int m0, int n0, int Kdim, char* sm, float (&acc)[4][4][4])
{
    const int tid  = threadIdx.x;
    const int wid  = tid >> 5, lane = tid & 31;
    const int wm   = wid >> 2, wn = wid & 3;
    const uint32_t sbase = smem_u32(sm);

    const int r  = tid >> 1, cg = tid & 1;
    const size_t ga = (size_t)(m0 + r) * Kdim + cg * 16;
    const size_t gb = (size_t)(n0 + r) * Kdim + cg * 16;
    const uint32_t soff = (uint32_t)(r * PITCH + cg * 32);

    const uint32_t aoff = (uint32_t)((wm * 64 + (lane & 15)) * PITCH + (lane >> 4) * 16);
    const uint32_t boff = (uint32_t)((wn * 32 + (lane & 7)) * PITCH + ((lane >> 3) & 1) * 16);

#define LOADC1(st, kc) do {                                                   \
    const uint32_t s0 = sbase + (uint32_t)(st) * STG1 + soff;                 \
    cp16(s0,            Ah + ga + (kc));                                      \
    cp16(s0 + 16,       Ah + ga + (kc) + 8);                                  \
    cp16(s0 + TSZ,      Bh + gb + (kc));                                      \
    cp16(s0 + TSZ + 16, Bh + gb + (kc) + 8);                                  \
    CP_COMMIT();                                                              \
} while (0)

    const int NC = Kdim / 32;
    LOADC1(0, 0);
    LOADC1(1, 32);
    LOADC1(2, 64);

#pragma unroll 1
    for (int c = 0; c < NC; c++) {
        CP_WAIT2();
        __syncthreads();
        const uint32_t tb = sbase + (uint32_t)(c & 3) * STG1;
#pragma unroll
        for (int k16 = 0; k16 < 2; k16++) {
            uint32_t ah[4][4], bh[4][2];
#pragma unroll
            for (int mi = 0; mi < 4; mi++)
                ldsm4(ah[mi], tb + aoff + mi * 16 * PITCH + k16 * 32);
#pragma unroll
            for (int ni = 0; ni < 4; ni++)
                ldsm2(bh[ni], tb + TSZ + boff + ni * 8 * PITCH + k16 * 32);
#pragma unroll
            for (int mi = 0; mi < 4; mi++)
#pragma unroll
                for (int ni = 0; ni < 4; ni++)
                    mma16816(acc[mi][ni], ah[mi], bh[ni]);
        }
        if (c + 3 < NC) LOADC1((c + 3) & 3, (c + 3) * 32);
    }
#undef LOADC1
}

// ---------------------------------------------------------------------------
// Conversions / transposes
// ---------------------------------------------------------------------------
__device__ __forceinline__ void split4(float4 v, __nv_bfloat162& h0, __nv_bfloat162& h1,
                                       __nv_bfloat162& l0, __nv_bfloat162& l1) {
    float f[4] = {v.x, v.y, v.z, v.w};
    __nv_bfloat16 h[4], l[4];
#pragma unroll
    for (int i = 0; i < 4; i++) {
        h[i] = __float2bfloat16(f[i]);
        l[i] = __float2bfloat16(f[i] - __bfloat162float(h[i]));
    }
    h0.x = h[0]; h0.y = h[1]; h1.x = h[2]; h1.y = h[3];
    l0.x = l[0]; l0.y = l[1]; l1.x = l[2]; l1.y = l[3];
}

__global__ void __launch_bounds__(256) convx_kernel(const float* __restrict__ X) {
    const size_t i = (size_t)blockIdx.x * 256 + threadIdx.x;
    float4 v = ((const float4*)X)[i];
    __nv_bfloat162 h0, h1, l0, l1;
    split4(v, h0, h1, l0, l1);
    ((__nv_bfloat162*)g_Xhi)[2 * i]     = h0;
    ((__nv_bfloat162*)g_Xhi)[2 * i + 1] = h1;
    ((__nv_bfloat162*)g_Xlo)[2 * i]     = l0;
    ((__nv_bfloat162*)g_Xlo)[2 * i + 1] = l1;
}

__global__ void __launch_bounds__(256) convv_kernel(const float* __restrict__ Wv) {
    const size_t i = (size_t)blockIdx.x * 256 + threadIdx.x;
    float4 v = ((const float4*)Wv)[i];
    __nv_bfloat162 h0, h1, l0, l1;
    split4(v, h0, h1, l0, l1);
    ((__nv_bfloat162*)g_Wvhi)[2 * i]     = h0;
    ((__nv_bfloat162*)g_Wvhi)[2 * i + 1] = h1;
    ((__nv_bfloat162*)g_Wvlo)[2 * i]     = l0;
    ((__nv_bfloat162*)g_Wvlo)[2 * i + 1] = l1;
}

// Transposed split copies of Wq, Wk: WT[e][h] = W[h][e], bf16 hi/lo.
__global__ void __launch_bounds__(256) transw_kernel(
    const float* __restrict__ Wq, const float* __restrict__ Wk)
{
    __shared__ float t[32][33];
    const int z = blockIdx.z;
    const float* W = z ? Wk : Wq;
    __nv_bfloat16* Th = z ? g_WkThi : g_WqThi;
    __nv_bfloat16* Tl = z ? g_WkTlo : g_WqTlo;
    const int e0 = blockIdx.x * 32, h0 = blockIdx.y * 32;
    const int tx = threadIdx.x & 31, ty = threadIdx.x >> 5;  // 32 x 8

#pragma unroll
    for (int i = ty; i < 32; i += 8)
        t[i][tx] = W[(size_t)(h0 + i) * EDIM + e0 + tx];
    __syncthreads();
#pragma unroll
    for (int i = ty; i < 32; i += 8) {
        float v = t[tx][i];                 // = W[h0+tx][e0+i]
        __nv_bfloat16 h = __float2bfloat16(v);
        __nv_bfloat16 l = __float2bfloat16(v - __bfloat162float(h));
        Th[(size_t)(e0 + i) * HDIM + h0 + tx] = h;
        Tl[(size_t)(e0 + i) * HDIM + h0 + tx] = l;
    }
}

// w1[e] = sum_h Wq[h,e]*bk[h],  w2[e] = sum_h Wk[h,e]*bq[h]
__global__ void __launch_bounds__(256) biasw_kernel(
    const float* __restrict__ bq, const float* __restrict__ bk)
{
    __shared__ float red[8];
    const int e = blockIdx.x, z = blockIdx.y;
    const __nv_bfloat16* Th = z ? g_WkThi : g_WqThi;
    const __nv_bfloat16* Tl = z ? g_WkTlo : g_WqTlo;
    const float* b = z ? bq : bk;
    float s = 0.0f;
    for (int h = threadIdx.x; h < HDIM; h += 256)
        s += (__bfloat162float(Th[(size_t)e * HDIM + h]) +
              __bfloat162float(Tl[(size_t)e * HDIM + h])) * b[h];
#pragma unroll
    for (int m = 16; m >= 1; m >>= 1) s += __shfl_xor_sync(0xffffffffu, s, m);
    if ((threadIdx.x & 31) == 0) red[threadIdx.x >> 5] = s;
    __syncthreads();
    if (threadIdx.x == 0) {
        float t = 0.0f;
#pragma unroll
        for (int i = 0; i < 8; i++) t += red[i];
        (z ? g_w2 : g_w1)[e] = t;
    }
}

__global__ void cscalar_kernel(const float* __restrict__ bq,
                               const float* __restrict__ bk)
{
    __shared__ float red[8];
    float s = 0.0f;
    for (int h = threadIdx.x; h < HDIM; h += 256) s += bq[h] * bk[h];
#pragma unroll
    for (int m = 16; m >= 1; m >>= 1) s += __shfl_xor_sync(0xffffffffu, s, m);
    if ((threadIdx.x & 31) == 0) red[threadIdx.x >> 5] = s;
    __syncthreads();
    if (threadIdx.x == 0) {
        float t = 0.0f;
#pragma unroll
        for (int i = 0; i < 8; i++) t += red[i];
        g_c = t;
    }
}

// alpha[l] = X[l].w1, beta[l] = X[l].w2  (exact fp32 inputs)
__global__ void __launch_bounds__(256) alphabeta_kernel(const float* __restrict__ X)
{
    __shared__ float reda[8], redb[8];
    const int l = blockIdx.x;
    float sa = 0.0f, sb = 0.0f;
    for (int e = threadIdx.x; e < EDIM; e += 256) {
        float x = X[(size_t)l * EDIM + e];
        sa += x * g_w1[e];
        sb += x * g_w2[e];
    }
#pragma unroll
    for (int m = 16; m >= 1; m >>= 1) {
        sa += __shfl_xor_sync(0xffffffffu, sa, m);
        sb += __shfl_xor_sync(0xffffffffu, sb, m);
    }
    if ((threadIdx.x & 31) == 0) { reda[threadIdx.x >> 5] = sa; redb[threadIdx.x >> 5] = sb; }
    __syncthreads();
    if (threadIdx.x == 0) {
        float ta = 0.0f, tb = 0.0f;
#pragma unroll
        for (int i = 0; i < 8; i++) { ta += reda[i]; tb += redb[i]; }
        g_alpha[l] = ta;
        g_beta[l]  = tb;
    }
}

// ---------------------------------------------------------------------------
// mgemm: Mt[e'][e] = sum_h Wk[h,e']*Wq[h,e]  (3-term).  grid (8, 8)
// ---------------------------------------------------------------------------
__global__ void __launch_bounds__(256, 2) mgemm_kernel()
{
    extern __shared__ char dynsm[];
    const int m0 = blockIdx.y * 128;   // e'
    const int n0 = blockIdx.x * 128;   // e

    float acc[4][4][4];
#pragma unroll
    for (int a = 0; a < 4; a++)
#pragma unroll
        for (int b = 0; b < 4; b++)
#pragma unroll
            for (int cc = 0; cc < 4; cc++) acc[a][b][cc] = 0.0f;

    run_tile3(g_WkThi, g_WkTlo, g_WqThi, g_WqTlo, m0, n0, HDIM, dynsm, acc);

    const int tid = threadIdx.x;
    const int wid = tid >> 5, lane = tid & 31;
    const int wm = wid >> 2, wn = wid & 3;

#pragma unroll
    for (int mi = 0; mi < 4; mi++) {
        const int r0 = m0 + wm * 64 + mi * 16 + (lane >> 2);
#pragma unroll
        for (int ni = 0; ni < 4; ni++) {
            const int gc = n0 + wn * 32 + ni * 8 + 2 * (lane & 3);
#pragma unroll
            for (int hh = 0; hh < 2; hh++) {
                const int rr = r0 + hh * 8;
                const float v0 = acc[mi][ni][2 * hh], v1 = acc[mi][ni][2 * hh + 1];
                __nv_bfloat162 h2, l2;
                h2.x = __float2bfloat16(v0);
                h2.y = __float2bfloat16(v1);
                l2.x = __float2bfloat16(v0 - __bfloat162float(h2.x));
                l2.y = __float2bfloat16(v1 - __bfloat162float(h2.y));
                *(__nv_bfloat162*)(g_Mhi + (size_t)rr * EDIM + gc) = h2;
                *(__nv_bfloat162*)(g_Mlo + (size_t)rr * EDIM + gc) = l2;
            }
        }
    }
}

// ---------------------------------------------------------------------------
// GEMM1: z=0: Qk = X*M^T (split bf16 out);  z=1: V = X*Wv^T + bv (fp32 out)
// grid (8, 128, 2)
// ---------------------------------------------------------------------------
__global__ void __launch_bounds__(256, 2) gemm1_kernel(const float* __restrict__ bv)
{
    extern __shared__ char dynsm[];
    const int z  = blockIdx.z;
    const int m0 = blockIdx.y * 128;
    const int n0 = blockIdx.x * 128;

    const __nv_bfloat16* Bh = z ? g_Wvhi : g_Mhi;
    const __nv_bfloat16* Bl = z ? g_Wvlo : g_Mlo;

    float acc[4][4][4];
#pragma unroll
    for (int a = 0; a < 4; a++)
#pragma unroll
        for (int b = 0; b < 4; b++)
#pragma unroll
            for (int cc = 0; cc < 4; cc++) acc[a][b][cc] = 0.0f;

    run_tile3(g_Xhi, g_Xlo, Bh, Bl, m0, n0, EDIM, dynsm, acc);

    const int tid = threadIdx.x;
    const int wid = tid >> 5, lane = tid & 31;
    const int wm = wid >> 2, wn = wid & 3;

#pragma unroll
    for (int mi = 0; mi < 4; mi++) {
        const int r0 = m0 + wm * 64 + mi * 16 + (lane >> 2);
#pragma unroll
        for (int ni = 0; ni < 4; ni++) {
            const int gc = n0 + wn * 32 + ni * 8 + 2 * (lane & 3);
            if (z == 1) {
                const float b0 = __ldg(&bv[gc]), b1 = __ldg(&bv[gc + 1]);
                *(float2*)(g_V + (size_t)r0 * HDIM + gc) =
                    make_float2(acc[mi][ni][0] + b0, acc[mi][ni][1] + b1);
                *(float2*)(g_V + (size_t)(r0 + 8) * HDIM + gc) =
                    make_float2(acc[mi][ni][2] + b0, acc[mi][ni][3] + b1);
            } else {
#pragma unroll
                for (int hh = 0; hh < 2; hh++) {
                    const int rr = r0 + hh * 8;
                    const float v0 = acc[mi][ni][2 * hh], v1 = acc[mi][ni][2 * hh + 1];
                    __nv_bfloat162 h2, l2;
                    h2.x = __float2bfloat16(v0);
                    h2.y = __float2bfloat16(v1);
                    l2.x = __float2bfloat16(v0 - __bfloat162float(h2.x));
                    l2.y = __float2bfloat16(v1 - __bfloat162float(h2.y));
                    *(__nv_bfloat162*)(g_Qkhi + (size_t)rr * EDIM + gc) = h2;
                    *(__nv_bfloat162*)(g_Qklo + (size_t)rr * EDIM + gc) = l2;
                }
            }
        }
    }
}

// ---------------------------------------------------------------------------
// Scores epilogue helper: exp + colsum (+ optional diag), with alpha/beta/c.
// ---------------------------------------------------------------------------
__device__ __forceinline__ void scores_epilogue(
    float (&acc)[4][4][4], int bz, int m0, int n0, bool diagblk)
{
    __shared__ float sred[128];
    const int tid = threadIdx.x;
    const int wid = tid >> 5, lane = tid & 31;
    const int wm = wid >> 2, wn = wid & 3;
    const float sc = 0.015625f;   // 1/sqrt(4096)
    const float cc = g_c;

    if (tid < 128) sred[tid] = 0.0f;

    float2 csum[4];
#pragma unroll
    for (int ni = 0; ni < 4; ni++) csum[ni] = make_float2(0.0f, 0.0f);

#pragma unroll
    for (int mi = 0; mi < 4; mi++) {
        const int lr = wm * 64 + mi * 16 + (lane >> 2);
        const float a0 = g_alpha[(size_t)bz * LSEQ + m0 + lr];
        const float a1 = g_alpha[(size_t)bz * LSEQ + m0 + lr + 8];
#pragma unroll
        for (int ni = 0; ni < 4; ni++) {
            const int lc = wn * 32 + ni * 8 + 2 * (lane & 3);
            const float b0 = g_beta[(size_t)bz * LSEQ + n0 + lc];
            const float b1 = g_beta[(size_t)bz * LSEQ + n0 + lc + 1];
            const float e00 = __expf((acc[mi][ni][0] + a0 + b0 + cc) * sc);
            const float e01 = __expf((acc[mi][ni][1] + a0 + b1 + cc) * sc);
            const float e10 = __expf((acc[mi][ni][2] + a1 + b0 + cc) * sc);
            const float e11 = __expf((acc[mi][ni][3] + a1 + b1 + cc) * sc);
            csum[ni].x += e00 + e10;
            csum[ni].y += e01 + e11;
            if (diagblk) {
                if (lr == lc)         g_diag[(size_t)bz * LSEQ + m0 + lr] = e00;
                if (lr == lc + 1)     g_diag[(size_t)bz * LSEQ + m0 + lr] = e01;
                if (lr + 8 == lc)     g_diag[(size_t)bz * LSEQ + m0 + lr + 8] = e10;
                if (lr + 8 == lc + 1) g_diag[(size_t)bz * LSEQ + m0 + lr + 8] = e11;
            }
        }
    }

    __syncthreads();   // sred init visible

#pragma unroll
    for (int ni = 0; ni < 4; ni++) {
#pragma unroll
        for (int m = 4; m <= 16; m <<= 1) {
            csum[ni].x += __shfl_xor_sync(0xffffffffu, csum[ni].x, m);
            csum[ni].y += __shfl_xor_sync(0xffffffffu, csum[ni].y, m);
        }
        if (lane < 4) {
            atomicAdd(&sred[wn * 32 + ni * 8 + 2 * lane],     csum[ni].x);
            atomicAdd(&sred[wn * 32 + ni * 8 + 2 * lane + 1], csum[ni].y);
        }
    }

    __syncthreads();
    if (tid < 128)
        atomicAdd(&g_colsum[(size_t)bz * LSEQ + n0 + tid], sred[tid]);
}

// ---------------------------------------------------------------------------
// GEMM2 off-diagonal: S = Qkhi * Xhi^T (1 MMA term).  grid (32, 32, NB)
// ---------------------------------------------------------------------------
__global__ void __launch_bounds__(256, 2) gemm2_off_kernel()
{
    if (blockIdx.x == blockIdx.y) return;   // diag handled separately
    extern __shared__ char dynsm[];

    const int bz = blockIdx.z;
    const int m0 = blockIdx.y * 128;
    const int n0 = blockIdx.x * 128;
    const size_t bo = (size_t)bz * LSEQ * EDIM;

    float acc[4][4][4];
#pragma unroll
    for (int a = 0; a < 4; a++)
#pragma unroll
        for (int b = 0; b < 4; b++)
#pragma unroll
            for (int cc = 0; cc < 4; cc++) acc[a][b][cc] = 0.0f;

    run_tile1(g_Qkhi + bo, g_Xhi + bo, m0, n0, EDIM, dynsm, acc);
    scores_epilogue(acc, bz, m0, n0, false);
}

// ---------------------------------------------------------------------------
// GEMM2 diagonal: 3-term split, diag extraction.  grid (32, NB)
// ---------------------------------------------------------------------------
__global__ void __launch_bounds__(256, 2) gemm2_diag_kernel()
{
    extern __shared__ char dynsm[];
    const int bz = blockIdx.y;
    const int m0 = blockIdx.x * 128;
    const size_t bo = (size_t)bz * LSEQ * EDIM;

    float acc[4][4][4];
#pragma unroll
    for (int a = 0; a < 4; a++)
#pragma unroll
        for (int b = 0; b < 4; b++)
#pragma unroll
            for (int cc = 0; cc < 4; cc++) acc[a][b][cc] = 0.0f;

    run_tile3(g_Qkhi + bo, g_Qklo + bo, g_Xhi + bo, g_Xlo + bo,
              m0, m0, EDIM, dynsm, acc);
    scores_epilogue(acc, bz, m0, m0, true);
}

// ---------------------------------------------------------------------------
__global__ void __launch_bounds__(256) finalize_kernel(float* __restrict__ out)
{
    const int row = blockIdx.x;
    const float scale = g_diag[row] / g_colsum[row];
    const float4* v = (const float4*)(g_V + (size_t)row * HDIM);
    float4* o = (float4*)(out + (size_t)row * HDIM);
    float4 x = v[threadIdx.x];
    x.x *= scale; x.y *= scale; x.z *= scale; x.w *= scale;
    o[threadIdx.x] = x;
}

__global__ void zero_kernel()
{
    const int i = blockIdx.x * 256 + threadIdx.x;
    if (i < ML) g_colsum[i] = 0.0f;
}

// ---------------------------------------------------------------------------
extern "C" void kernel_launch(void* const* d_in, const int* in_sizes, int n_in,
                              void* d_out, int out_size)
{
    (void)in_sizes; (void)n_in; (void)out_size;
    const float* X  = (const float*)d_in[0];
    const float* Wq = (const float*)d_in[1];
    const float* bq = (const float*)d_in[2];
    const float* Wk = (const float*)d_in[3];
    const float* bk = (const float*)d_in[4];
    const float* Wv = (const float*)d_in[5];
    const float* bv = (const float*)d_in[6];
    float* out = (float*)d_out;

    // Idempotent host-side attribute setup (capture-safe, not stream ops).
    cudaFuncSetAttribute(mgemm_kernel,      cudaFuncAttributeMaxDynamicSharedMemorySize, DYNSMEM);
    cudaFuncSetAttribute(gemm1_kernel,      cudaFuncAttributeMaxDynamicSharedMemorySize, DYNSMEM);
    cudaFuncSetAttribute(gemm2_off_kernel,  cudaFuncAttributeMaxDynamicSharedMemorySize, DYNSMEM);
    cudaFuncSetAttribute(gemm2_diag_kernel, cudaFuncAttributeMaxDynamicSharedMemorySize, DYNSMEM);
    // Max carveout so 2 CTAs x 80KB smem co-reside per SM.
    cudaFuncSetAttribute(mgemm_kernel,      cudaFuncAttributePreferredSharedMemoryCarveout, 100);
    cudaFuncSetAttribute(gemm1_kernel,      cudaFuncAttributePreferredSharedMemoryCarveout, 100);
    cudaFuncSetAttribute(gemm2_off_kernel,  cudaFuncAttributePreferredSharedMemoryCarveout, 100);
    cudaFuncSetAttribute(gemm2_diag_kernel, cudaFuncAttributePreferredSharedMemoryCarveout, 100);

    zero_kernel<<<(ML + 255) / 256, 256>>>();

    convx_kernel<<<(ML * EDIM / 4) / 256, 256>>>(X);
    convv_kernel<<<(HDIM * EDIM / 4) / 256, 256>>>(Wv);

    dim3 gt(EDIM / 32, HDIM / 32, 2);
    transw_kernel<<<gt, 256>>>(Wq, Wk);

    dim3 gb(EDIM, 2);
    biasw_kernel<<<gb, 256>>>(bq, bk);
    cscalar_kernel<<<1, 256>>>(bq, bk);

    dim3 gm(EDIM / 128, EDIM / 128);
    mgemm_kernel<<<gm, 256, DYNSMEM>>>();

    alphabeta_kernel<<<ML, 256>>>(X);

    dim3 g1(EDIM / 128, ML / 128, 2);
    gemm1_kernel<<<g1, 256, DYNSMEM>>>(bv);

    dim3 g2(LSEQ / 128, LSEQ / 128, NB);
    gemm2_off_kernel<<<g2, 256, DYNSMEM>>>();

    dim3 g2d(LSEQ / 128, NB);
    gemm2_diag_kernel<<<g2d, 256, DYNSMEM>>>();

    finalize_kernel<<<ML, 256>>>(out);
}